// round 1
// baseline (speedup 1.0000x reference)
#include <cuda_runtime.h>
#include <cuda_bf16.h>
#include <math.h>

// ---------------- problem dims ----------------
#define B_   16
#define L_   512
#define ENC  7
#define DM   512
#define DIN  1024
#define DSTATE 16
#define DCONV 4
#define DTRANK 32
#define COUT 7
#define PRED 96
#define NTOK (B_*L_)          // 8192
#define MOUT (B_*PRED)        // 1536

// ---------------- scratch (device globals; allocation-free) ----------------
__device__ float g_mean[B_*ENC];
__device__ float g_std[B_*ENC];
__device__ float g_x  [NTOK*DM];        // post-embed + pos
__device__ float g_xz [NTOK*2*DIN];     // [xm | z]
__device__ float g_u  [NTOK*DIN];       // silu(conv(xm))
__device__ float g_dbc[NTOK*(DTRANK+2*DSTATE)]; // 64 wide
__device__ float g_dt [NTOK*DIN];
__device__ float g_yg [MOUT*DIN];       // gated y, last 96 steps only
__device__ float g_x2 [MOUT*DM];

// ---------------- helpers ----------------
__device__ __forceinline__ float softplusf(float x){
    return x > 20.f ? x : log1pf(expf(x));
}

// ---------------- kernel 1: per-(b,c) mean/std over L ----------------
__global__ void meanstd_kernel(const float* __restrict__ x_enc,
                               float* __restrict__ mean, float* __restrict__ stdv){
    int b = blockIdx.x / ENC, c = blockIdx.x % ENC;
    float s = 0.f, s2 = 0.f;
    for (int l = threadIdx.x; l < L_; l += 32){
        float v = x_enc[(b*L_ + l)*ENC + c];
        s += v; s2 += v*v;
    }
    #pragma unroll
    for (int o = 16; o > 0; o >>= 1){
        s  += __shfl_xor_sync(0xffffffffu, s,  o);
        s2 += __shfl_xor_sync(0xffffffffu, s2, o);
    }
    if (threadIdx.x == 0){
        float m = s * (1.f/L_);
        float var = s2 * (1.f/L_) - m*m;
        mean[blockIdx.x] = m;
        stdv[blockIdx.x] = sqrtf(var + 1e-5f);
    }
}

// ---------------- kernel 2: normalize + wrap-pad 3-tap embed + pos emb ----------------
__global__ void embed_kernel(const float* __restrict__ x_enc,
                             const float* __restrict__ W_emb,
                             const float* __restrict__ mean,
                             const float* __restrict__ stdv,
                             float* __restrict__ xout){
    int l = blockIdx.x, b = blockIdx.y;
    __shared__ float s[3*ENC];
    int tid = threadIdx.x;
    if (tid < 3*ENC){
        int k = tid / ENC, c = tid % ENC;
        int lm = (l - 1 + k + L_) & (L_-1);
        s[tid] = (x_enc[(b*L_ + lm)*ENC + c] - mean[b*ENC + c]) / stdv[b*ENC + c];
    }
    __syncthreads();
    const float NEG_LN1E4_OVER_D = -9.210340371976184f / (float)DM;
    for (int d = tid; d < DM; d += blockDim.x){
        int i = d >> 1;
        float freq = expf((float)(2*i) * NEG_LN1E4_OVER_D);
        float ang  = (float)l * freq;
        float acc  = (d & 1) ? cosf(ang) : sinf(ang);
        #pragma unroll
        for (int k = 0; k < 3; k++)
            #pragma unroll
            for (int c = 0; c < ENC; c++)
                acc = fmaf(s[k*ENC + c], W_emb[(k*ENC + c)*DM + d], acc);
        xout[((b*L_) + l)*DM + d] = acc;
    }
}

// ---------------- generic tiled SGEMM ----------------
// EPI: 0 = plain store, 1 = softplus(acc + bias[n])
template<int BM,int BN,int BK,int TM,int TN,int EPI>
__global__ void sgemm_k(const float* __restrict__ A, const float* __restrict__ B,
                        float* __restrict__ C, int K, int lda, int ldb, int ldc,
                        const float* __restrict__ bias){
    constexpr int THREADS = (BM/TM)*(BN/TN);
    __shared__ float As[BK][BM];
    __shared__ float Bs[BK][BN];
    const int tid = threadIdx.x;
    const int tx  = tid % (BN/TN);
    const int ty  = tid / (BN/TN);
    const float* Ab = A + (long)blockIdx.y * BM * lda;
    const float* Bb = B + blockIdx.x * BN;
    float acc[TM][TN];
    #pragma unroll
    for (int i=0;i<TM;i++)
        #pragma unroll
        for (int j=0;j<TN;j++) acc[i][j]=0.f;

    for (int k0 = 0; k0 < K; k0 += BK){
        constexpr int A4 = BM*BK/4;
        #pragma unroll
        for (int i = tid; i < A4; i += THREADS){
            int r = i / (BK/4), c4 = i % (BK/4);
            float4 v = *reinterpret_cast<const float4*>(Ab + (long)r*lda + k0 + c4*4);
            As[c4*4+0][r]=v.x; As[c4*4+1][r]=v.y; As[c4*4+2][r]=v.z; As[c4*4+3][r]=v.w;
        }
        constexpr int B4 = BK*BN/4;
        #pragma unroll
        for (int i = tid; i < B4; i += THREADS){
            int r = i / (BN/4), c4 = i % (BN/4);
            *reinterpret_cast<float4*>(&Bs[r][c4*4]) =
                *reinterpret_cast<const float4*>(Bb + (long)(k0+r)*ldb + c4*4);
        }
        __syncthreads();
        #pragma unroll
        for (int k = 0; k < BK; k++){
            float a[TM], bv[TN];
            #pragma unroll
            for (int i=0;i<TM;i++) a[i] = As[k][ty*TM+i];
            #pragma unroll
            for (int j=0;j<TN;j++) bv[j] = Bs[k][tx*TN+j];
            #pragma unroll
            for (int i=0;i<TM;i++)
                #pragma unroll
                for (int j=0;j<TN;j++)
                    acc[i][j] = fmaf(a[i], bv[j], acc[i][j]);
        }
        __syncthreads();
    }
    #pragma unroll
    for (int i=0;i<TM;i++){
        long m = (long)blockIdx.y*BM + ty*TM + i;
        #pragma unroll
        for (int j=0;j<TN;j++){
            int n = blockIdx.x*BN + tx*TN + j;
            float v = acc[i][j];
            if (EPI == 1) v = softplusf(v + bias[n]);
            C[m*ldc + n] = v;
        }
    }
}

// ---------------- kernel: depthwise causal conv(4) + bias + silu ----------------
__global__ void conv_kernel(const float* __restrict__ xz,
                            const float* __restrict__ conv_w,
                            const float* __restrict__ conv_b,
                            float* __restrict__ u){
    int l = blockIdx.x, b = blockIdx.y;
    for (int d = threadIdx.x; d < DIN; d += blockDim.x){
        float acc = conv_b[d];
        #pragma unroll
        for (int k = 0; k < DCONV; k++){
            int lm = l - (DCONV-1) + k;
            if (lm >= 0)
                acc = fmaf(xz[((long)(b*L_) + lm)*(2*DIN) + d], conv_w[k*DIN + d], acc);
        }
        float sg = 1.f / (1.f + __expf(-acc));
        u[((long)(b*L_) + l)*DIN + d] = acc * sg;
    }
}

// ---------------- kernel: selective scan + fused gate for last PRED steps ----------------
__global__ void scan_kernel(const float* __restrict__ dbc,
                            const float* __restrict__ dt,
                            const float* __restrict__ u,
                            const float* __restrict__ xz,
                            const float* __restrict__ A_log,
                            const float* __restrict__ Dp,
                            float* __restrict__ yg){
    const int b = blockIdx.x;
    const int d = blockIdx.y * 128 + threadIdx.x;
    float h[DSTATE], An[DSTATE];
    #pragma unroll
    for (int n = 0; n < DSTATE; n++){
        h[n]  = 0.f;
        An[n] = -expf(A_log[d*DSTATE + n]);
    }
    const float Dv = Dp[d];
    __shared__ float sB[64][DSTATE];
    __shared__ float sC[64][DSTATE];
    for (int t0 = 0; t0 < L_; t0 += 64){
        __syncthreads();
        for (int i = threadIdx.x; i < 64*2*DSTATE; i += 128){
            int tt = i >> 5, j = i & 31;
            float v = dbc[((long)(b*L_) + (t0+tt))*64 + DTRANK + j];
            if (j < DSTATE) sB[tt][j] = v; else sC[tt][j-DSTATE] = v;
        }
        __syncthreads();
        for (int tt = 0; tt < 64; tt++){
            int t = t0 + tt;
            long row = (long)(b*L_) + t;
            float dtv = dt[row*DIN + d];
            float uv  = u [row*DIN + d];
            float dtu = dtv * uv;
            float y = 0.f;
            #pragma unroll
            for (int n = 0; n < DSTATE; n++){
                float dA = __expf(dtv * An[n]);
                h[n] = fmaf(dA, h[n], dtu * sB[tt][n]);
                y = fmaf(h[n], sC[tt][n], y);
            }
            if (t >= L_ - PRED){
                float zv = xz[row*(2*DIN) + DIN + d];
                float sg = 1.f / (1.f + __expf(-zv));
                yg[((long)(b*PRED) + (t - (L_-PRED)))*DIN + d] = (y + uv*Dv) * (zv * sg);
            }
        }
    }
}

// ---------------- kernel: head GEMM (K=512 -> 7) + denorm ----------------
__global__ void head_kernel(const float* __restrict__ x2,
                            const float* __restrict__ W_head,
                            const float* __restrict__ mean,
                            const float* __restrict__ stdv,
                            float* __restrict__ out){
    int m = blockIdx.x;              // 0..1535
    __shared__ float s[DM];
    for (int k = threadIdx.x; k < DM; k += blockDim.x)
        s[k] = x2[(long)m*DM + k];
    __syncthreads();
    if (threadIdx.x < COUT){
        int c = threadIdx.x;
        float acc = 0.f;
        for (int k = 0; k < DM; k++)
            acc = fmaf(s[k], W_head[k*COUT + c], acc);
        int b = m / PRED;
        out[(long)m*COUT + c] = acc * stdv[b*ENC + c] + mean[b*ENC + c];
    }
}

// ---------------- launcher ----------------
extern "C" void kernel_launch(void* const* d_in, const int* in_sizes, int n_in,
                              void* d_out, int out_size){
    const float* x_enc  = (const float*)d_in[0];
    const float* W_emb  = (const float*)d_in[1];
    const float* W_in   = (const float*)d_in[2];
    const float* conv_w = (const float*)d_in[3];
    const float* conv_b = (const float*)d_in[4];
    const float* W_xproj= (const float*)d_in[5];
    const float* W_dt   = (const float*)d_in[6];
    const float* b_dt   = (const float*)d_in[7];
    const float* A_log  = (const float*)d_in[8];
    const float* Dp     = (const float*)d_in[9];
    const float* W_out  = (const float*)d_in[10];
    const float* W_head = (const float*)d_in[11];
    float* out = (float*)d_out;

    float *p_mean,*p_std,*p_x,*p_xz,*p_u,*p_dbc,*p_dt,*p_yg,*p_x2;
    cudaGetSymbolAddress((void**)&p_mean, g_mean);
    cudaGetSymbolAddress((void**)&p_std,  g_std);
    cudaGetSymbolAddress((void**)&p_x,    g_x);
    cudaGetSymbolAddress((void**)&p_xz,   g_xz);
    cudaGetSymbolAddress((void**)&p_u,    g_u);
    cudaGetSymbolAddress((void**)&p_dbc,  g_dbc);
    cudaGetSymbolAddress((void**)&p_dt,   g_dt);
    cudaGetSymbolAddress((void**)&p_yg,   g_yg);
    cudaGetSymbolAddress((void**)&p_x2,   g_x2);

    // 1) per-(b,c) stats
    meanstd_kernel<<<B_*ENC, 32>>>(x_enc, p_mean, p_std);

    // 2) normalize + 3-tap token embed + pos emb -> g_x (8192 x 512)
    embed_kernel<<<dim3(L_, B_), 256>>>(x_enc, W_emb, p_mean, p_std, p_x);

    // 3) xz = x @ W_in  (8192x512 @ 512x2048)
    sgemm_k<128,64,16,8,4,0><<<dim3((2*DIN)/64, NTOK/128), 256>>>(
        p_x, W_in, p_xz, DM, DM, 2*DIN, 2*DIN, nullptr);

    // 4) depthwise causal conv + silu -> g_u
    conv_kernel<<<dim3(L_, B_), 256>>>(p_xz, conv_w, conv_b, p_u);

    // 5) dbc = u @ W_xproj  (8192x1024 @ 1024x64)
    sgemm_k<64,64,16,4,4,0><<<dim3(1, NTOK/64), 256>>>(
        p_u, W_xproj, p_dbc, DIN, DIN, 64, 64, nullptr);

    // 6) dt = softplus(dbc[:, :32] @ W_dt + b_dt)  (8192x32 @ 32x1024)
    sgemm_k<64,64,32,4,4,1><<<dim3(DIN/64, NTOK/64), 256>>>(
        p_dbc, W_dt, p_dt, DTRANK, 64, DIN, DIN, b_dt);

    // 7) selective scan + fused (y + u*D)*silu(z), write last 96 steps compactly
    scan_kernel<<<dim3(B_, DIN/128), 128>>>(p_dbc, p_dt, p_u, p_xz, A_log, Dp, p_yg);

    // 8) x2 = yg @ W_out  (1536x1024 @ 1024x512)
    sgemm_k<64,64,16,4,4,0><<<dim3(DM/64, MOUT/64), 256>>>(
        p_yg, W_out, p_x2, DIN, DIN, DM, DM, nullptr);

    // 9) out = (x2 @ W_head) * std + mean
    head_kernel<<<MOUT, 256>>>(p_x2, W_head, p_mean, p_std, out);
}

// round 3
// speedup vs baseline: 1.3319x; 1.3319x over previous
#include <cuda_runtime.h>
#include <cuda_bf16.h>
#include <math.h>
#include <stdint.h>

// ---------------- problem dims ----------------
#define B_   16
#define L_   512
#define ENC  7
#define DM   512
#define DIN  1024
#define DSTATE 16
#define DCONV 4
#define DTRANK 32
#define COUT 7
#define PRED 96
#define NTOK (B_*L_)          // 8192
#define MOUT (B_*PRED)        // 1536

// ---------------- scratch (device globals; allocation-free) ----------------
__device__ float g_mean[B_*ENC];
__device__ float g_std[B_*ENC];
__device__ float g_x  [NTOK*DM];        // post-embed + pos
__device__ float g_xz [NTOK*2*DIN];     // [xm | z]
__device__ float g_u  [NTOK*DIN];       // silu(conv(xm))
__device__ float g_dbc[NTOK*(DTRANK+2*DSTATE)]; // 64 wide
__device__ float g_dt [NTOK*DIN];
__device__ float g_yg [MOUT*DIN];       // gated y, last 96 steps only
__device__ float g_x2 [MOUT*DM];

// ---------------- helpers ----------------
__device__ __forceinline__ float softplusf(float x){
    return x > 20.f ? x : log1pf(expf(x));
}
__device__ __forceinline__ uint32_t f2tf(float x){
    uint32_t r; asm("cvt.rna.tf32.f32 %0, %1;" : "=r"(r) : "f"(x)); return r;
}
__device__ __forceinline__ void mma_tf32(float* c, const uint32_t* a, const uint32_t* b){
    asm volatile(
      "mma.sync.aligned.m16n8k8.row.col.f32.tf32.tf32.f32 "
      "{%0,%1,%2,%3}, {%4,%5,%6,%7}, {%8,%9}, {%0,%1,%2,%3};\n"
      : "+f"(c[0]), "+f"(c[1]), "+f"(c[2]), "+f"(c[3])
      : "r"(a[0]), "r"(a[1]), "r"(a[2]), "r"(a[3]), "r"(b[0]), "r"(b[1]));
}

// ---------------- kernel 1: per-(b,c) mean/std over L ----------------
__global__ void meanstd_kernel(const float* __restrict__ x_enc,
                               float* __restrict__ mean, float* __restrict__ stdv){
    int b = blockIdx.x / ENC, c = blockIdx.x % ENC;
    float s = 0.f, s2 = 0.f;
    for (int l = threadIdx.x; l < L_; l += 32){
        float v = x_enc[(b*L_ + l)*ENC + c];
        s += v; s2 += v*v;
    }
    #pragma unroll
    for (int o = 16; o > 0; o >>= 1){
        s  += __shfl_xor_sync(0xffffffffu, s,  o);
        s2 += __shfl_xor_sync(0xffffffffu, s2, o);
    }
    if (threadIdx.x == 0){
        float m = s * (1.f/L_);
        float var = s2 * (1.f/L_) - m*m;
        mean[blockIdx.x] = m;
        stdv[blockIdx.x] = sqrtf(var + 1e-5f);
    }
}

// ---------------- kernel 2: normalize + wrap-pad 3-tap embed + pos emb ----------------
__global__ void embed_kernel(const float* __restrict__ x_enc,
                             const float* __restrict__ W_emb,
                             const float* __restrict__ mean,
                             const float* __restrict__ stdv,
                             float* __restrict__ xout){
    int l = blockIdx.x, b = blockIdx.y;
    __shared__ float s[3*ENC];
    int tid = threadIdx.x;
    if (tid < 3*ENC){
        int k = tid / ENC, c = tid % ENC;
        int lm = (l - 1 + k + L_) & (L_-1);
        s[tid] = (x_enc[(b*L_ + lm)*ENC + c] - mean[b*ENC + c]) / stdv[b*ENC + c];
    }
    __syncthreads();
    const float NEG_LN1E4_OVER_D = -9.210340371976184f / (float)DM;
    for (int d = tid; d < DM; d += blockDim.x){
        int i = d >> 1;
        float freq = expf((float)(2*i) * NEG_LN1E4_OVER_D);
        float ang  = (float)l * freq;
        float acc  = (d & 1) ? cosf(ang) : sinf(ang);
        #pragma unroll
        for (int k = 0; k < 3; k++)
            #pragma unroll
            for (int c = 0; c < ENC; c++)
                acc = fmaf(s[k*ENC + c], W_emb[(k*ENC + c)*DM + d], acc);
        xout[((b*L_) + l)*DM + d] = acc;
    }
}

// ---------------- tf32 tensor-core GEMM ----------------
// C[M,N] = A[M,K] @ B[K,N], row-major, arbitrary ld.
// Block tile 128x64xBK16, 8 warps (4x2), warp tile 32x32 (2x4 m16n8k8 atoms).
// EPI: 0 = plain store, 1 = softplus(acc + bias[n])
template<int EPI>
__global__ void tf32gemm_k(const float* __restrict__ A, const float* __restrict__ B,
                           float* __restrict__ C, int K, int lda, int ldb, int ldc,
                           const float* __restrict__ bias){
    constexpr int BM = 128, BN = 64, BK = 16;
    constexpr int ASTR = BK + 4;   // 20 floats: conflict-free frag loads
    constexpr int BSTR = BN + 8;   // 72 floats: conflict-free frag loads
    __shared__ uint32_t As[BM*ASTR];
    __shared__ uint32_t Bs[BK*BSTR];

    const int tid  = threadIdx.x;
    const int wid  = tid >> 5, lane = tid & 31;
    const int wm   = wid >> 1, wn = wid & 1;        // 4x2 warp grid
    const int m0   = wm*32, n0 = wn*32;
    const int tg   = lane >> 2, kq = lane & 3;       // groupID, tid-in-group

    float acc[2][4][4];
    #pragma unroll
    for (int mi=0;mi<2;mi++)
        #pragma unroll
        for (int ni=0;ni<4;ni++)
            #pragma unroll
            for (int r=0;r<4;r++) acc[mi][ni][r]=0.f;

    const float* Ab = A + (long)blockIdx.y * BM * lda;
    const float* Bb = B + blockIdx.x * BN;

    for (int k0 = 0; k0 < K; k0 += BK){
        // A tile: BM x BK (512 float4, 2 per thread), convert to tf32 on store
        #pragma unroll
        for (int i = tid; i < BM*BK/4; i += 256){
            int r = i >> 2, c4 = i & 3;
            float4 v = *reinterpret_cast<const float4*>(Ab + (long)r*lda + k0 + c4*4);
            uint4 w = make_uint4(f2tf(v.x), f2tf(v.y), f2tf(v.z), f2tf(v.w));
            *reinterpret_cast<uint4*>(&As[r*ASTR + c4*4]) = w;
        }
        // B tile: BK x BN (256 float4, 1 per thread)
        #pragma unroll
        for (int i = tid; i < BK*BN/4; i += 256){
            int r = i >> 4, c4 = i & 15;
            float4 v = *reinterpret_cast<const float4*>(Bb + (long)(k0+r)*ldb + c4*4);
            uint4 w = make_uint4(f2tf(v.x), f2tf(v.y), f2tf(v.z), f2tf(v.w));
            *reinterpret_cast<uint4*>(&Bs[r*BSTR + c4*4]) = w;
        }
        __syncthreads();

        #pragma unroll
        for (int kk = 0; kk < BK; kk += 8){
            uint32_t af[2][4], bf[4][2];
            #pragma unroll
            for (int mi=0; mi<2; mi++){
                int mr = m0 + mi*16;
                af[mi][0] = As[(mr + tg    )*ASTR + kk + kq    ];
                af[mi][1] = As[(mr + 8 + tg)*ASTR + kk + kq    ];
                af[mi][2] = As[(mr + tg    )*ASTR + kk + 4 + kq];
                af[mi][3] = As[(mr + 8 + tg)*ASTR + kk + 4 + kq];
            }
            #pragma unroll
            for (int ni=0; ni<4; ni++){
                int nc = n0 + ni*8 + tg;
                bf[ni][0] = Bs[(kk + kq    )*BSTR + nc];
                bf[ni][1] = Bs[(kk + 4 + kq)*BSTR + nc];
            }
            #pragma unroll
            for (int mi=0; mi<2; mi++)
                #pragma unroll
                for (int ni=0; ni<4; ni++)
                    mma_tf32(acc[mi][ni], af[mi], bf[ni]);
        }
        __syncthreads();
    }

    // epilogue
    #pragma unroll
    for (int mi=0; mi<2; mi++){
        long r0 = (long)blockIdx.y*BM + m0 + mi*16 + tg;
        #pragma unroll
        for (int ni=0; ni<4; ni++){
            int c = blockIdx.x*BN + n0 + ni*8 + 2*kq;
            float v0 = acc[mi][ni][0], v1 = acc[mi][ni][1];
            float v2 = acc[mi][ni][2], v3 = acc[mi][ni][3];
            if (EPI == 1){
                v0 = softplusf(v0 + bias[c]);   v1 = softplusf(v1 + bias[c+1]);
                v2 = softplusf(v2 + bias[c]);   v3 = softplusf(v3 + bias[c+1]);
            }
            C[ r0   *ldc + c    ] = v0;
            C[ r0   *ldc + c + 1] = v1;
            C[(r0+8)*ldc + c    ] = v2;
            C[(r0+8)*ldc + c + 1] = v3;
        }
    }
}

// ---------------- kernel: depthwise causal conv(4) + bias + silu ----------------
__global__ void conv_kernel(const float* __restrict__ xz,
                            const float* __restrict__ conv_w,
                            const float* __restrict__ conv_b,
                            float* __restrict__ u){
    int l = blockIdx.x, b = blockIdx.y;
    for (int d = threadIdx.x; d < DIN; d += blockDim.x){
        float acc = conv_b[d];
        #pragma unroll
        for (int k = 0; k < DCONV; k++){
            int lm = l - (DCONV-1) + k;
            if (lm >= 0)
                acc = fmaf(xz[((long)(b*L_) + lm)*(2*DIN) + d], conv_w[k*DIN + d], acc);
        }
        float sg = 1.f / (1.f + __expf(-acc));
        u[((long)(b*L_) + l)*DIN + d] = acc * sg;
    }
}

// ---------------- kernel: selective scan + fused gate for last PRED steps ----------------
__global__ void scan_kernel(const float* __restrict__ dbc,
                            const float* __restrict__ dt,
                            const float* __restrict__ u,
                            const float* __restrict__ xz,
                            const float* __restrict__ A_log,
                            const float* __restrict__ Dp,
                            float* __restrict__ yg){
    const int b = blockIdx.x;
    const int d = blockIdx.y * 128 + threadIdx.x;
    float h[DSTATE], An[DSTATE];
    #pragma unroll
    for (int n = 0; n < DSTATE; n++){
        h[n]  = 0.f;
        An[n] = -expf(A_log[d*DSTATE + n]);
    }
    const float Dv = Dp[d];
    __shared__ float sB[64][DSTATE];
    __shared__ float sC[64][DSTATE];
    for (int t0 = 0; t0 < L_; t0 += 64){
        __syncthreads();
        for (int i = threadIdx.x; i < 64*2*DSTATE; i += 128){
            int tt = i >> 5, j = i & 31;
            float v = dbc[((long)(b*L_) + (t0+tt))*64 + DTRANK + j];
            if (j < DSTATE) sB[tt][j] = v; else sC[tt][j-DSTATE] = v;
        }
        __syncthreads();
        for (int tt = 0; tt < 64; tt++){
            int t = t0 + tt;
            long row = (long)(b*L_) + t;
            float dtv = dt[row*DIN + d];
            float uv  = u [row*DIN + d];
            float dtu = dtv * uv;
            float y = 0.f;
            #pragma unroll
            for (int n = 0; n < DSTATE; n++){
                float dA = __expf(dtv * An[n]);
                h[n] = fmaf(dA, h[n], dtu * sB[tt][n]);
                y = fmaf(h[n], sC[tt][n], y);
            }
            if (t >= L_ - PRED){
                float zv = xz[row*(2*DIN) + DIN + d];
                float sg = 1.f / (1.f + __expf(-zv));
                yg[((long)(b*PRED) + (t - (L_-PRED)))*DIN + d] = (y + uv*Dv) * (zv * sg);
            }
        }
    }
}

// ---------------- kernel: head GEMM (K=512 -> 7) + denorm ----------------
__global__ void head_kernel(const float* __restrict__ x2,
                            const float* __restrict__ W_head,
                            const float* __restrict__ mean,
                            const float* __restrict__ stdv,
                            float* __restrict__ out){
    int m = blockIdx.x;              // 0..1535
    __shared__ float s[DM];
    for (int k = threadIdx.x; k < DM; k += blockDim.x)
        s[k] = x2[(long)m*DM + k];
    __syncthreads();
    if (threadIdx.x < COUT){
        int c = threadIdx.x;
        float acc = 0.f;
        for (int k = 0; k < DM; k++)
            acc = fmaf(s[k], W_head[k*COUT + c], acc);
        int b = m / PRED;
        out[(long)m*COUT + c] = acc * stdv[b*ENC + c] + mean[b*ENC + c];
    }
}

// ---------------- launcher ----------------
extern "C" void kernel_launch(void* const* d_in, const int* in_sizes, int n_in,
                              void* d_out, int out_size){
    const float* x_enc  = (const float*)d_in[0];
    const float* W_emb  = (const float*)d_in[1];
    const float* W_in   = (const float*)d_in[2];
    const float* conv_w = (const float*)d_in[3];
    const float* conv_b = (const float*)d_in[4];
    const float* W_xproj= (const float*)d_in[5];
    const float* W_dt   = (const float*)d_in[6];
    const float* b_dt   = (const float*)d_in[7];
    const float* A_log  = (const float*)d_in[8];
    const float* Dp     = (const float*)d_in[9];
    const float* W_out  = (const float*)d_in[10];
    const float* W_head = (const float*)d_in[11];
    float* out = (float*)d_out;

    float *p_mean,*p_std,*p_x,*p_xz,*p_u,*p_dbc,*p_dt,*p_yg,*p_x2;
    cudaGetSymbolAddress((void**)&p_mean, g_mean);
    cudaGetSymbolAddress((void**)&p_std,  g_std);
    cudaGetSymbolAddress((void**)&p_x,    g_x);
    cudaGetSymbolAddress((void**)&p_xz,   g_xz);
    cudaGetSymbolAddress((void**)&p_u,    g_u);
    cudaGetSymbolAddress((void**)&p_dbc,  g_dbc);
    cudaGetSymbolAddress((void**)&p_dt,   g_dt);
    cudaGetSymbolAddress((void**)&p_yg,   g_yg);
    cudaGetSymbolAddress((void**)&p_x2,   g_x2);

    // 1) per-(b,c) stats
    meanstd_kernel<<<B_*ENC, 32>>>(x_enc, p_mean, p_std);

    // 2) normalize + 3-tap token embed + pos emb -> g_x (8192 x 512)
    embed_kernel<<<dim3(L_, B_), 256>>>(x_enc, W_emb, p_mean, p_std, p_x);

    // 3) xz = x @ W_in  (8192x512 @ 512x2048) -- tf32 tensor cores
    tf32gemm_k<0><<<dim3((2*DIN)/64, NTOK/128), 256>>>(
        p_x, W_in, p_xz, DM, DM, 2*DIN, 2*DIN, nullptr);

    // 4) depthwise causal conv + silu -> g_u
    conv_kernel<<<dim3(L_, B_), 256>>>(p_xz, conv_w, conv_b, p_u);

    // 5) dbc = u @ W_xproj  (8192x1024 @ 1024x64) -- tf32
    tf32gemm_k<0><<<dim3(1, NTOK/128), 256>>>(
        p_u, W_xproj, p_dbc, DIN, DIN, 64, 64, nullptr);

    // 6) dt = softplus(dbc[:, :32] @ W_dt + b_dt)  (8192x32 @ 32x1024) -- tf32
    tf32gemm_k<1><<<dim3(DIN/64, NTOK/128), 256>>>(
        p_dbc, W_dt, p_dt, DTRANK, 64, DIN, DIN, b_dt);

    // 7) selective scan + fused (y + u*D)*silu(z), write last 96 steps compactly
    scan_kernel<<<dim3(B_, DIN/128), 128>>>(p_dbc, p_dt, p_u, p_xz, A_log, Dp, p_yg);

    // 8) x2 = yg @ W_out  (1536x1024 @ 1024x512) -- tf32
    tf32gemm_k<0><<<dim3(DM/64, MOUT/128), 256>>>(
        p_yg, W_out, p_x2, DIN, DIN, DM, DM, nullptr);

    // 9) out = (x2 @ W_head) * std + mean
    head_kernel<<<MOUT, 256>>>(p_x2, W_head, p_mean, p_std, out);
}

// round 4
// speedup vs baseline: 1.8842x; 1.4147x over previous
#include <cuda_runtime.h>
#include <cuda_bf16.h>
#include <math.h>
#include <stdint.h>

// ---------------- problem dims ----------------
#define B_   16
#define L_   512
#define ENC  7
#define DM   512
#define DIN  1024
#define DSTATE 16
#define DCONV 4
#define DTRANK 32
#define COUT 7
#define PRED 96
#define NTOK (B_*L_)          // 8192
#define MOUT (B_*PRED)        // 1536

// ---------------- scratch (device globals; allocation-free) ----------------
__device__ float g_mean[B_*ENC];
__device__ float g_std[B_*ENC];
__device__ __nv_bfloat16 g_xb [NTOK*DM];      // post-embed + pos (bf16, GEMM A)
__device__ float g_xz [NTOK*2*DIN];           // [xm | z]
__device__ float g_u  [NTOK*DIN];             // silu(conv(xm)) fp32 (scan)
__device__ __nv_bfloat16 g_ub [NTOK*DIN];     // same in bf16 (GEMM A)
__device__ float g_dbc[NTOK*(DTRANK+2*DSTATE)];
__device__ float g_dt [NTOK*DIN];
__device__ __nv_bfloat16 g_ygb[MOUT*DIN];     // gated y (bf16, GEMM A)
__device__ float g_x2 [MOUT*DM];
__device__ __nv_bfloat16 g_winb [DM*2*DIN];   // bf16 weights
__device__ __nv_bfloat16 g_wxpb [DIN*(DTRANK+2*DSTATE)];
__device__ __nv_bfloat16 g_woutb[DIN*DM];

// ---------------- helpers ----------------
__device__ __forceinline__ float softplusf(float x){
    return x > 20.f ? x : log1pf(expf(x));
}
__device__ __forceinline__ uint32_t f2tf(float x){
    uint32_t r; asm("cvt.rna.tf32.f32 %0, %1;" : "=r"(r) : "f"(x)); return r;
}
__device__ __forceinline__ void mma_tf32(float* c, const uint32_t* a, const uint32_t* b){
    asm volatile(
      "mma.sync.aligned.m16n8k8.row.col.f32.tf32.tf32.f32 "
      "{%0,%1,%2,%3}, {%4,%5,%6,%7}, {%8,%9}, {%0,%1,%2,%3};\n"
      : "+f"(c[0]), "+f"(c[1]), "+f"(c[2]), "+f"(c[3])
      : "r"(a[0]), "r"(a[1]), "r"(a[2]), "r"(a[3]), "r"(b[0]), "r"(b[1]));
}
__device__ __forceinline__ void mma_bf16(float* c, const uint32_t* a, const uint32_t* b){
    asm volatile(
      "mma.sync.aligned.m16n8k16.row.col.f32.bf16.bf16.f32 "
      "{%0,%1,%2,%3}, {%4,%5,%6,%7}, {%8,%9}, {%0,%1,%2,%3};\n"
      : "+f"(c[0]), "+f"(c[1]), "+f"(c[2]), "+f"(c[3])
      : "r"(a[0]), "r"(a[1]), "r"(a[2]), "r"(a[3]), "r"(b[0]), "r"(b[1]));
}
__device__ __forceinline__ void ldsm4(uint32_t* r, uint32_t addr){
    asm volatile("ldmatrix.sync.aligned.m8n8.x4.shared.b16 {%0,%1,%2,%3}, [%4];"
        : "=r"(r[0]), "=r"(r[1]), "=r"(r[2]), "=r"(r[3]) : "r"(addr));
}
__device__ __forceinline__ void ldsm4t(uint32_t* r, uint32_t addr){
    asm volatile("ldmatrix.sync.aligned.m8n8.x4.trans.shared.b16 {%0,%1,%2,%3}, [%4];"
        : "=r"(r[0]), "=r"(r[1]), "=r"(r[2]), "=r"(r[3]) : "r"(addr));
}
__device__ __forceinline__ void cp16(uint32_t dst, const void* src){
    asm volatile("cp.async.cg.shared.global [%0], [%1], 16;" :: "r"(dst), "l"(src));
}

// ---------------- kernel: fp32 -> bf16 weight conversion (3 arrays) ----------------
__global__ void cvt3_kernel(const float* __restrict__ a, __nv_bfloat16* __restrict__ ab,
                            const float* __restrict__ b, __nv_bfloat16* __restrict__ bb,
                            const float* __restrict__ c, __nv_bfloat16* __restrict__ cb){
    int i = (blockIdx.x*256 + threadIdx.x)*4;
    if (i < DM*2*DIN){
        float4 v = *(const float4*)(a+i);
        *(__nv_bfloat162*)(ab+i)   = __floats2bfloat162_rn(v.x, v.y);
        *(__nv_bfloat162*)(ab+i+2) = __floats2bfloat162_rn(v.z, v.w);
    }
    if (i < DIN*64){
        float4 v = *(const float4*)(b+i);
        *(__nv_bfloat162*)(bb+i)   = __floats2bfloat162_rn(v.x, v.y);
        *(__nv_bfloat162*)(bb+i+2) = __floats2bfloat162_rn(v.z, v.w);
    }
    if (i < DIN*DM){
        float4 v = *(const float4*)(c+i);
        *(__nv_bfloat162*)(cb+i)   = __floats2bfloat162_rn(v.x, v.y);
        *(__nv_bfloat162*)(cb+i+2) = __floats2bfloat162_rn(v.z, v.w);
    }
}

// ---------------- kernel 1: per-(b,c) mean/std over L ----------------
__global__ void meanstd_kernel(const float* __restrict__ x_enc,
                               float* __restrict__ mean, float* __restrict__ stdv){
    int b = blockIdx.x / ENC, c = blockIdx.x % ENC;
    float s = 0.f, s2 = 0.f;
    for (int l = threadIdx.x; l < L_; l += 32){
        float v = x_enc[(b*L_ + l)*ENC + c];
        s += v; s2 += v*v;
    }
    #pragma unroll
    for (int o = 16; o > 0; o >>= 1){
        s  += __shfl_xor_sync(0xffffffffu, s,  o);
        s2 += __shfl_xor_sync(0xffffffffu, s2, o);
    }
    if (threadIdx.x == 0){
        float m = s * (1.f/L_);
        float var = s2 * (1.f/L_) - m*m;
        mean[blockIdx.x] = m;
        stdv[blockIdx.x] = sqrtf(var + 1e-5f);
    }
}

// ---------------- kernel 2: normalize + wrap-pad 3-tap embed + pos emb (bf16 out) ---
__global__ void embed_kernel(const float* __restrict__ x_enc,
                             const float* __restrict__ W_emb,
                             const float* __restrict__ mean,
                             const float* __restrict__ stdv,
                             __nv_bfloat16* __restrict__ xout){
    int l = blockIdx.x, b = blockIdx.y;
    __shared__ float s[3*ENC];
    int tid = threadIdx.x;
    if (tid < 3*ENC){
        int k = tid / ENC, c = tid % ENC;
        int lm = (l - 1 + k + L_) & (L_-1);
        s[tid] = (x_enc[(b*L_ + lm)*ENC + c] - mean[b*ENC + c]) / stdv[b*ENC + c];
    }
    __syncthreads();
    const float NEG_LN1E4_OVER_D = -9.210340371976184f / (float)DM;
    for (int d = tid; d < DM; d += blockDim.x){
        int i = d >> 1;
        float freq = expf((float)(2*i) * NEG_LN1E4_OVER_D);
        float ang  = (float)l * freq;
        float acc  = (d & 1) ? cosf(ang) : sinf(ang);
        #pragma unroll
        for (int k = 0; k < 3; k++)
            #pragma unroll
            for (int c = 0; c < ENC; c++)
                acc = fmaf(s[k*ENC + c], W_emb[(k*ENC + c)*DM + d], acc);
        xout[((b*L_) + l)*DM + d] = __float2bfloat16(acc);
    }
}

// ---------------- bf16 tensor-core GEMM, cp.async double-buffered ----------------
// C[M,N](fp32) = A[M,K](bf16) @ B[K,N](bf16); BM=128, BK=32, 8 warps.
// Swizzled smem + ldmatrix (A non-trans, B trans), conflict-free.
template<int BN, int WM, int WN>
__global__ __launch_bounds__(256) void bf16gemm_k(
    const __nv_bfloat16* __restrict__ A, const __nv_bfloat16* __restrict__ B,
    float* __restrict__ C, int K, int lda, int ldb, int ldc)
{
    constexpr int BM = 128, BK = 32;
    constexpr int WARPS_N = BN/WN;
    constexpr int MT = WM/16, NT = WN/8, NT2 = WN/16;
    constexpr int BCH = BN/8;                 // B 16B-chunks per row
    __shared__ __nv_bfloat16 As[2][BM*BK];
    __shared__ __nv_bfloat16 Bs[2][BK*BN];

    const int tid = threadIdx.x, lane = tid & 31, wid = tid >> 5;
    const int wm = wid / WARPS_N, wn = wid % WARPS_N;
    const int quad = lane >> 3, r8 = lane & 7;
    const uint32_t aBase = (uint32_t)__cvta_generic_to_shared(&As[0][0]);
    const uint32_t bBase = (uint32_t)__cvta_generic_to_shared(&Bs[0][0]);

    const __nv_bfloat16* Ag = A + (long)blockIdx.y * BM * lda;
    const __nv_bfloat16* Bg = B + blockIdx.x * BN;

    float acc[MT][NT][4] = {};

    auto load_stage = [&](int st, int k0){
        #pragma unroll
        for (int i = tid; i < BM*4; i += 256){            // A: 128 rows x 4 chunks
            int m = i >> 2, c = i & 3;
            uint32_t d = aBase + (uint32_t)(st*(BM*BK*2) + (m*BK + ((c ^ ((m>>1)&3))<<3))*2);
            cp16(d, Ag + (long)m*lda + k0 + c*8);
        }
        #pragma unroll
        for (int i = tid; i < BK*BCH; i += 256){          // B: 32 rows x BCH chunks
            int k = i / BCH, c = i % BCH;
            uint32_t d = bBase + (uint32_t)(st*(BK*BN*2) + (k*BN + ((c ^ (k&7))<<3))*2);
            cp16(d, Bg + (long)(k0+k)*ldb + c*8);
        }
    };

    const int KT = K / BK;
    load_stage(0, 0);
    asm volatile("cp.async.commit_group;");
    for (int kt = 0; kt < KT; kt++){
        const int st = kt & 1;
        if (kt + 1 < KT){
            load_stage(st^1, (kt+1)*BK);
            asm volatile("cp.async.commit_group;");
            asm volatile("cp.async.wait_group 1;");
        } else {
            asm volatile("cp.async.wait_group 0;");
        }
        __syncthreads();
        const uint32_t aSt = aBase + st*(BM*BK*2);
        const uint32_t bSt = bBase + st*(BK*BN*2);
        #pragma unroll
        for (int ks = 0; ks < 2; ks++){
            uint32_t af[MT][4], bfr[NT2][4];
            #pragma unroll
            for (int mi = 0; mi < MT; mi++){
                int row = wm*WM + mi*16 + r8 + ((quad&1)<<3);
                int kc  = ks*2 + (quad>>1);
                uint32_t ad = aSt + (uint32_t)((row*BK + (((kc ^ ((row>>1)&3)))<<3))*2);
                ldsm4(af[mi], ad);
            }
            #pragma unroll
            for (int nj = 0; nj < NT2; nj++){
                int rk  = ks*16 + r8 + ((quad&1)<<3);
                int col = wn*WN + nj*16 + ((quad>>1)<<3);
                uint32_t bd = bSt + (uint32_t)((rk*BN + (((col>>3) ^ (rk&7))<<3))*2);
                ldsm4t(bfr[nj], bd);
            }
            #pragma unroll
            for (int mi = 0; mi < MT; mi++)
                #pragma unroll
                for (int nj = 0; nj < NT2; nj++){
                    mma_bf16(acc[mi][2*nj],   af[mi], bfr[nj]);
                    mma_bf16(acc[mi][2*nj+1], af[mi], bfr[nj]+2);
                }
        }
        __syncthreads();
    }

    const int tg = lane >> 2, tq = lane & 3;
    #pragma unroll
    for (int mi = 0; mi < MT; mi++){
        long r0 = (long)blockIdx.y*BM + wm*WM + mi*16 + tg;
        #pragma unroll
        for (int ni = 0; ni < NT; ni++){
            int c = blockIdx.x*BN + wn*WN + ni*8 + 2*tq;
            C[ r0   *ldc + c    ] = acc[mi][ni][0];
            C[ r0   *ldc + c + 1] = acc[mi][ni][1];
            C[(r0+8)*ldc + c    ] = acc[mi][ni][2];
            C[(r0+8)*ldc + c + 1] = acc[mi][ni][3];
        }
    }
}

// ---------------- tf32 GEMM (kept for the tiny K=32 dt projection) ----------------
template<int EPI>
__global__ void tf32gemm_k(const float* __restrict__ A, const float* __restrict__ B,
                           float* __restrict__ C, int K, int lda, int ldb, int ldc,
                           const float* __restrict__ bias){
    constexpr int BM = 128, BN = 64, BK = 16;
    constexpr int ASTR = BK + 4;
    constexpr int BSTR = BN + 8;
    __shared__ uint32_t As[BM*ASTR];
    __shared__ uint32_t Bs[BK*BSTR];

    const int tid  = threadIdx.x;
    const int wid  = tid >> 5, lane = tid & 31;
    const int wm   = wid >> 1, wn = wid & 1;
    const int m0   = wm*32, n0 = wn*32;
    const int tg   = lane >> 2, kq = lane & 3;

    float acc[2][4][4];
    #pragma unroll
    for (int mi=0;mi<2;mi++)
        #pragma unroll
        for (int ni=0;ni<4;ni++)
            #pragma unroll
            for (int r=0;r<4;r++) acc[mi][ni][r]=0.f;

    const float* Ab = A + (long)blockIdx.y * BM * lda;
    const float* Bb = B + blockIdx.x * BN;

    for (int k0 = 0; k0 < K; k0 += BK){
        #pragma unroll
        for (int i = tid; i < BM*BK/4; i += 256){
            int r = i >> 2, c4 = i & 3;
            float4 v = *reinterpret_cast<const float4*>(Ab + (long)r*lda + k0 + c4*4);
            uint4 w = make_uint4(f2tf(v.x), f2tf(v.y), f2tf(v.z), f2tf(v.w));
            *reinterpret_cast<uint4*>(&As[r*ASTR + c4*4]) = w;
        }
        #pragma unroll
        for (int i = tid; i < BK*BN/4; i += 256){
            int r = i >> 4, c4 = i & 15;
            float4 v = *reinterpret_cast<const float4*>(Bb + (long)(k0+r)*ldb + c4*4);
            uint4 w = make_uint4(f2tf(v.x), f2tf(v.y), f2tf(v.z), f2tf(v.w));
            *reinterpret_cast<uint4*>(&Bs[r*BSTR + c4*4]) = w;
        }
        __syncthreads();
        #pragma unroll
        for (int kk = 0; kk < BK; kk += 8){
            uint32_t af[2][4], bf[4][2];
            #pragma unroll
            for (int mi=0; mi<2; mi++){
                int mr = m0 + mi*16;
                af[mi][0] = As[(mr + tg    )*ASTR + kk + kq    ];
                af[mi][1] = As[(mr + 8 + tg)*ASTR + kk + kq    ];
                af[mi][2] = As[(mr + tg    )*ASTR + kk + 4 + kq];
                af[mi][3] = As[(mr + 8 + tg)*ASTR + kk + 4 + kq];
            }
            #pragma unroll
            for (int ni=0; ni<4; ni++){
                int nc = n0 + ni*8 + tg;
                bf[ni][0] = Bs[(kk + kq    )*BSTR + nc];
                bf[ni][1] = Bs[(kk + 4 + kq)*BSTR + nc];
            }
            #pragma unroll
            for (int mi=0; mi<2; mi++)
                #pragma unroll
                for (int ni=0; ni<4; ni++)
                    mma_tf32(acc[mi][ni], af[mi], bf[ni]);
        }
        __syncthreads();
    }
    #pragma unroll
    for (int mi=0; mi<2; mi++){
        long r0 = (long)blockIdx.y*BM + m0 + mi*16 + tg;
        #pragma unroll
        for (int ni=0; ni<4; ni++){
            int c = blockIdx.x*BN + n0 + ni*8 + 2*kq;
            float v0 = acc[mi][ni][0], v1 = acc[mi][ni][1];
            float v2 = acc[mi][ni][2], v3 = acc[mi][ni][3];
            if (EPI == 1){
                v0 = softplusf(v0 + bias[c]);   v1 = softplusf(v1 + bias[c+1]);
                v2 = softplusf(v2 + bias[c]);   v3 = softplusf(v3 + bias[c+1]);
            }
            C[ r0   *ldc + c    ] = v0;
            C[ r0   *ldc + c + 1] = v1;
            C[(r0+8)*ldc + c    ] = v2;
            C[(r0+8)*ldc + c + 1] = v3;
        }
    }
}

// ---------------- kernel: depthwise causal conv(4) + bias + silu (float4) --------
__global__ void conv_kernel(const float* __restrict__ xz,
                            const float* __restrict__ conv_w,
                            const float* __restrict__ conv_b,
                            float* __restrict__ u,
                            __nv_bfloat16* __restrict__ ub){
    int l = blockIdx.x, b = blockIdx.y;
    int d = threadIdx.x * 4;                     // 256 threads cover DIN=1024
    long row = (long)(b*L_) + l;
    float4 acc = *reinterpret_cast<const float4*>(conv_b + d);
    #pragma unroll
    for (int k = 0; k < DCONV; k++){
        int lm = l - (DCONV-1) + k;
        if (lm >= 0){
            float4 xv = *reinterpret_cast<const float4*>(xz + ((long)(b*L_)+lm)*(2*DIN) + d);
            float4 wv = *reinterpret_cast<const float4*>(conv_w + k*DIN + d);
            acc.x = fmaf(xv.x, wv.x, acc.x);
            acc.y = fmaf(xv.y, wv.y, acc.y);
            acc.z = fmaf(xv.z, wv.z, acc.z);
            acc.w = fmaf(xv.w, wv.w, acc.w);
        }
    }
    float4 o;
    o.x = acc.x / (1.f + __expf(-acc.x));
    o.y = acc.y / (1.f + __expf(-acc.y));
    o.z = acc.z / (1.f + __expf(-acc.z));
    o.w = acc.w / (1.f + __expf(-acc.w));
    *reinterpret_cast<float4*>(u + row*DIN + d) = o;
    *(__nv_bfloat162*)(ub + row*DIN + d)     = __floats2bfloat162_rn(o.x, o.y);
    *(__nv_bfloat162*)(ub + row*DIN + d + 2) = __floats2bfloat162_rn(o.z, o.w);
}

// ---------------- kernel: selective scan + fused gate for last PRED steps --------
__global__ void scan_kernel(const float* __restrict__ dbc,
                            const float* __restrict__ dt,
                            const float* __restrict__ u,
                            const float* __restrict__ xz,
                            const float* __restrict__ A_log,
                            const float* __restrict__ Dp,
                            __nv_bfloat16* __restrict__ yg){
    const int b = blockIdx.x;
    const int d = blockIdx.y * 128 + threadIdx.x;
    float h[DSTATE], An[DSTATE];
    #pragma unroll
    for (int n = 0; n < DSTATE; n++){
        h[n]  = 0.f;
        An[n] = -expf(A_log[d*DSTATE + n]);
    }
    const float Dv = Dp[d];
    __shared__ float sB[64][DSTATE];
    __shared__ float sC[64][DSTATE];
    for (int t0 = 0; t0 < L_; t0 += 64){
        __syncthreads();
        for (int i = threadIdx.x; i < 64*2*DSTATE; i += 128){
            int tt = i >> 5, j = i & 31;
            float v = dbc[((long)(b*L_) + (t0+tt))*64 + DTRANK + j];
            if (j < DSTATE) sB[tt][j] = v; else sC[tt][j-DSTATE] = v;
        }
        __syncthreads();
        for (int tt = 0; tt < 64; tt++){
            int t = t0 + tt;
            long row = (long)(b*L_) + t;
            float dtv = dt[row*DIN + d];
            float uv  = u [row*DIN + d];
            float dtu = dtv * uv;
            float y = 0.f;
            #pragma unroll
            for (int n = 0; n < DSTATE; n++){
                float dA = __expf(dtv * An[n]);
                h[n] = fmaf(dA, h[n], dtu * sB[tt][n]);
                y = fmaf(h[n], sC[tt][n], y);
            }
            if (t >= L_ - PRED){
                float zv = xz[row*(2*DIN) + DIN + d];
                float sg = 1.f / (1.f + __expf(-zv));
                yg[((long)(b*PRED) + (t - (L_-PRED)))*DIN + d] =
                    __float2bfloat16((y + uv*Dv) * (zv * sg));
            }
        }
    }
}

// ---------------- kernel: head GEMM (K=512 -> 7) + denorm ----------------
__global__ void head_kernel(const float* __restrict__ x2,
                            const float* __restrict__ W_head,
                            const float* __restrict__ mean,
                            const float* __restrict__ stdv,
                            float* __restrict__ out){
    int m = blockIdx.x;
    __shared__ float s[DM];
    for (int k = threadIdx.x; k < DM; k += blockDim.x)
        s[k] = x2[(long)m*DM + k];
    __syncthreads();
    if (threadIdx.x < COUT){
        int c = threadIdx.x;
        float acc = 0.f;
        for (int k = 0; k < DM; k++)
            acc = fmaf(s[k], W_head[k*COUT + c], acc);
        int b = m / PRED;
        out[(long)m*COUT + c] = acc * stdv[b*ENC + c] + mean[b*ENC + c];
    }
}

// ---------------- launcher ----------------
extern "C" void kernel_launch(void* const* d_in, const int* in_sizes, int n_in,
                              void* d_out, int out_size){
    const float* x_enc  = (const float*)d_in[0];
    const float* W_emb  = (const float*)d_in[1];
    const float* W_in   = (const float*)d_in[2];
    const float* conv_w = (const float*)d_in[3];
    const float* conv_b = (const float*)d_in[4];
    const float* W_xproj= (const float*)d_in[5];
    const float* W_dt   = (const float*)d_in[6];
    const float* b_dt   = (const float*)d_in[7];
    const float* A_log  = (const float*)d_in[8];
    const float* Dp     = (const float*)d_in[9];
    const float* W_out  = (const float*)d_in[10];
    const float* W_head = (const float*)d_in[11];
    float* out = (float*)d_out;

    float *p_mean,*p_std,*p_xz,*p_u,*p_dbc,*p_dt,*p_x2;
    __nv_bfloat16 *p_xb,*p_ub,*p_ygb,*p_winb,*p_wxpb,*p_woutb;
    cudaGetSymbolAddress((void**)&p_mean, g_mean);
    cudaGetSymbolAddress((void**)&p_std,  g_std);
    cudaGetSymbolAddress((void**)&p_xb,   g_xb);
    cudaGetSymbolAddress((void**)&p_xz,   g_xz);
    cudaGetSymbolAddress((void**)&p_u,    g_u);
    cudaGetSymbolAddress((void**)&p_ub,   g_ub);
    cudaGetSymbolAddress((void**)&p_dbc,  g_dbc);
    cudaGetSymbolAddress((void**)&p_dt,   g_dt);
    cudaGetSymbolAddress((void**)&p_ygb,  g_ygb);
    cudaGetSymbolAddress((void**)&p_x2,   g_x2);
    cudaGetSymbolAddress((void**)&p_winb, g_winb);
    cudaGetSymbolAddress((void**)&p_wxpb, g_wxpb);
    cudaGetSymbolAddress((void**)&p_woutb,g_woutb);

    // 0) weights fp32 -> bf16
    cvt3_kernel<<<(DM*2*DIN)/(256*4), 256>>>(W_in, p_winb, W_xproj, p_wxpb, W_out, p_woutb);

    // 1) per-(b,c) stats
    meanstd_kernel<<<B_*ENC, 32>>>(x_enc, p_mean, p_std);

    // 2) normalize + 3-tap token embed + pos emb -> g_xb (bf16)
    embed_kernel<<<dim3(L_, B_), 256>>>(x_enc, W_emb, p_mean, p_std, p_xb);

    // 3) xz = x @ W_in  (8192x512 @ 512x2048) -- bf16 mma, cp.async pipeline
    bf16gemm_k<128,64,32><<<dim3((2*DIN)/128, NTOK/128), 256>>>(
        p_xb, p_winb, p_xz, DM, DM, 2*DIN, 2*DIN);

    // 4) depthwise causal conv + silu -> g_u (fp32) + g_ub (bf16)
    conv_kernel<<<dim3(L_, B_), 256>>>(p_xz, conv_w, conv_b, p_u, p_ub);

    // 5) dbc = u @ W_xproj  (8192x1024 @ 1024x64) -- bf16
    bf16gemm_k<64,32,32><<<dim3(1, NTOK/128), 256>>>(
        p_ub, p_wxpb, p_dbc, DIN, DIN, 64, 64);

    // 6) dt = softplus(dbc[:, :32] @ W_dt + b_dt)  (8192x32 @ 32x1024) -- tf32
    tf32gemm_k<1><<<dim3(DIN/64, NTOK/128), 256>>>(
        p_dbc, W_dt, p_dt, DTRANK, 64, DIN, DIN, b_dt);

    // 7) selective scan + fused (y + u*D)*silu(z) -> g_ygb (bf16, last 96 steps)
    scan_kernel<<<dim3(B_, DIN/128), 128>>>(p_dbc, p_dt, p_u, p_xz, A_log, Dp, p_ygb);

    // 8) x2 = yg @ W_out  (1536x1024 @ 1024x512) -- bf16
    bf16gemm_k<64,32,32><<<dim3(DM/64, MOUT/128), 256>>>(
        p_ygb, p_woutb, p_x2, DIN, DIN, DM, DM);

    // 9) out = (x2 @ W_head) * std + mean
    head_kernel<<<MOUT, 256>>>(p_x2, W_head, p_mean, p_std, out);
}

// round 5
// speedup vs baseline: 3.1143x; 1.6528x over previous
#include <cuda_runtime.h>
#include <cuda_bf16.h>
#include <math.h>
#include <stdint.h>

// ---------------- problem dims ----------------
#define B_   16
#define L_   512
#define ENC  7
#define DM   512
#define DIN  1024
#define DSTATE 16
#define DCONV 4
#define DTRANK 32
#define COUT 7
#define PRED 96
#define NTOK (B_*L_)          // 8192
#define MOUT (B_*PRED)        // 1536
#define NCH  8                // scan chunks
#define CHK  64               // chunk length

// ---------------- scratch (device globals; allocation-free) ----------------
__device__ float g_mean[B_*ENC];
__device__ float g_std[B_*ENC];
__device__ float g_pos[L_*DM];                // positional embedding table
__device__ __nv_bfloat16 g_xb [NTOK*DM];      // post-embed + pos (bf16, GEMM A)
__device__ float g_xz [NTOK*2*DIN];           // [xm | z]
__device__ float g_u  [NTOK*DIN];             // silu(conv(xm)) fp32 (scan)
__device__ __nv_bfloat16 g_ub [NTOK*DIN];     // same in bf16 (GEMM A)
__device__ float g_dbc[NTOK*(DTRANK+2*DSTATE)];
__device__ float g_dt [NTOK*DIN];
__device__ float g_hend[B_*NCH*DSTATE*DIN];   // per-chunk local end states
__device__ float g_S   [B_*NCH*DIN];          // per-chunk sum(dt)
__device__ float g_hin [2*B_*DSTATE*DIN];     // h_in for chunks 6,7
__device__ __nv_bfloat16 g_ygb[MOUT*DIN];     // gated y (bf16, GEMM A)
__device__ float g_x2 [MOUT*DM];
__device__ __nv_bfloat16 g_winb [DM*2*DIN];   // bf16 weights
__device__ __nv_bfloat16 g_wxpb [DIN*(DTRANK+2*DSTATE)];
__device__ __nv_bfloat16 g_woutb[DIN*DM];

// ---------------- helpers ----------------
__device__ __forceinline__ float softplusf(float x){
    return x > 20.f ? x : log1pf(expf(x));
}
__device__ __forceinline__ uint32_t f2tf(float x){
    uint32_t r; asm("cvt.rna.tf32.f32 %0, %1;" : "=r"(r) : "f"(x)); return r;
}
__device__ __forceinline__ void mma_tf32(float* c, const uint32_t* a, const uint32_t* b){
    asm volatile(
      "mma.sync.aligned.m16n8k8.row.col.f32.tf32.tf32.f32 "
      "{%0,%1,%2,%3}, {%4,%5,%6,%7}, {%8,%9}, {%0,%1,%2,%3};\n"
      : "+f"(c[0]), "+f"(c[1]), "+f"(c[2]), "+f"(c[3])
      : "r"(a[0]), "r"(a[1]), "r"(a[2]), "r"(a[3]), "r"(b[0]), "r"(b[1]));
}
__device__ __forceinline__ void mma_bf16(float* c, const uint32_t* a, const uint32_t* b){
    asm volatile(
      "mma.sync.aligned.m16n8k16.row.col.f32.bf16.bf16.f32 "
      "{%0,%1,%2,%3}, {%4,%5,%6,%7}, {%8,%9}, {%0,%1,%2,%3};\n"
      : "+f"(c[0]), "+f"(c[1]), "+f"(c[2]), "+f"(c[3])
      : "r"(a[0]), "r"(a[1]), "r"(a[2]), "r"(a[3]), "r"(b[0]), "r"(b[1]));
}
__device__ __forceinline__ void ldsm4(uint32_t* r, uint32_t addr){
    asm volatile("ldmatrix.sync.aligned.m8n8.x4.shared.b16 {%0,%1,%2,%3}, [%4];"
        : "=r"(r[0]), "=r"(r[1]), "=r"(r[2]), "=r"(r[3]) : "r"(addr));
}
__device__ __forceinline__ void ldsm4t(uint32_t* r, uint32_t addr){
    asm volatile("ldmatrix.sync.aligned.m8n8.x4.trans.shared.b16 {%0,%1,%2,%3}, [%4];"
        : "=r"(r[0]), "=r"(r[1]), "=r"(r[2]), "=r"(r[3]) : "r"(addr));
}
__device__ __forceinline__ void cp16(uint32_t dst, const void* src){
    asm volatile("cp.async.cg.shared.global [%0], [%1], 16;" :: "r"(dst), "l"(src));
}

// ---------------- kernel: fp32 -> bf16 weight conversion (3 arrays) ----------------
__global__ void cvt3_kernel(const float* __restrict__ a, __nv_bfloat16* __restrict__ ab,
                            const float* __restrict__ b, __nv_bfloat16* __restrict__ bb,
                            const float* __restrict__ c, __nv_bfloat16* __restrict__ cb){
    int i = (blockIdx.x*256 + threadIdx.x)*4;
    if (i < DM*2*DIN){
        float4 v = *(const float4*)(a+i);
        *(__nv_bfloat162*)(ab+i)   = __floats2bfloat162_rn(v.x, v.y);
        *(__nv_bfloat162*)(ab+i+2) = __floats2bfloat162_rn(v.z, v.w);
    }
    if (i < DIN*64){
        float4 v = *(const float4*)(b+i);
        *(__nv_bfloat162*)(bb+i)   = __floats2bfloat162_rn(v.x, v.y);
        *(__nv_bfloat162*)(bb+i+2) = __floats2bfloat162_rn(v.z, v.w);
    }
    if (i < DIN*DM){
        float4 v = *(const float4*)(c+i);
        *(__nv_bfloat162*)(cb+i)   = __floats2bfloat162_rn(v.x, v.y);
        *(__nv_bfloat162*)(cb+i+2) = __floats2bfloat162_rn(v.z, v.w);
    }
}

// ---------------- kernel: positional table (once per launch) ----------------
__global__ void pos_kernel(float* __restrict__ pos){
    int l = blockIdx.x;
    const float NEG_LN1E4_OVER_D = -9.210340371976184f / (float)DM;
    for (int d = threadIdx.x; d < DM; d += blockDim.x){
        float freq = expf((float)(2*(d>>1)) * NEG_LN1E4_OVER_D);
        float ang  = (float)l * freq;
        pos[l*DM + d] = (d & 1) ? cosf(ang) : sinf(ang);
    }
}

// ---------------- kernel 1: per-(b,c) mean/std over L ----------------
__global__ void meanstd_kernel(const float* __restrict__ x_enc,
                               float* __restrict__ mean, float* __restrict__ stdv){
    int b = blockIdx.x / ENC, c = blockIdx.x % ENC;
    float s = 0.f, s2 = 0.f;
    for (int l = threadIdx.x; l < L_; l += 32){
        float v = x_enc[(b*L_ + l)*ENC + c];
        s += v; s2 += v*v;
    }
    #pragma unroll
    for (int o = 16; o > 0; o >>= 1){
        s  += __shfl_xor_sync(0xffffffffu, s,  o);
        s2 += __shfl_xor_sync(0xffffffffu, s2, o);
    }
    if (threadIdx.x == 0){
        float m = s * (1.f/L_);
        float var = s2 * (1.f/L_) - m*m;
        mean[blockIdx.x] = m;
        stdv[blockIdx.x] = sqrtf(var + 1e-5f);
    }
}

// ---------------- kernel 2: normalize + 3-tap embed + pos table (bf16 out) --------
__global__ void embed_kernel(const float* __restrict__ x_enc,
                             const float* __restrict__ W_emb,
                             const float* __restrict__ mean,
                             const float* __restrict__ stdv,
                             const float* __restrict__ pos,
                             __nv_bfloat16* __restrict__ xout){
    int l = blockIdx.x, b = blockIdx.y;
    __shared__ float s[3*ENC];
    int tid = threadIdx.x;
    if (tid < 3*ENC){
        int k = tid / ENC, c = tid % ENC;
        int lm = (l - 1 + k + L_) & (L_-1);
        s[tid] = (x_enc[(b*L_ + lm)*ENC + c] - mean[b*ENC + c]) / stdv[b*ENC + c];
    }
    __syncthreads();
    for (int d = tid; d < DM; d += blockDim.x){
        float acc = pos[l*DM + d];
        #pragma unroll
        for (int k = 0; k < 3; k++)
            #pragma unroll
            for (int c = 0; c < ENC; c++)
                acc = fmaf(s[k*ENC + c], W_emb[(k*ENC + c)*DM + d], acc);
        xout[((b*L_) + l)*DM + d] = __float2bfloat16(acc);
    }
}

// ---------------- bf16 tensor-core GEMM, cp.async double-buffered ----------------
template<int BM, int BN, int WM, int WN>
__global__ __launch_bounds__(256) void bf16gemm_k(
    const __nv_bfloat16* __restrict__ A, const __nv_bfloat16* __restrict__ B,
    float* __restrict__ C, int K, int lda, int ldb, int ldc)
{
    constexpr int BK = 32;
    constexpr int WARPS_N = BN/WN;
    constexpr int MT = WM/16, NT = WN/8, NT2 = WN/16;
    constexpr int BCH = BN/8;
    __shared__ __nv_bfloat16 As[2][BM*BK];
    __shared__ __nv_bfloat16 Bs[2][BK*BN];

    const int tid = threadIdx.x, lane = tid & 31, wid = tid >> 5;
    const int wm = wid / WARPS_N, wn = wid % WARPS_N;
    const int quad = lane >> 3, r8 = lane & 7;
    const uint32_t aBase = (uint32_t)__cvta_generic_to_shared(&As[0][0]);
    const uint32_t bBase = (uint32_t)__cvta_generic_to_shared(&Bs[0][0]);

    const __nv_bfloat16* Ag = A + (long)blockIdx.y * BM * lda;
    const __nv_bfloat16* Bg = B + blockIdx.x * BN;

    float acc[MT][NT][4] = {};

    auto load_stage = [&](int st, int k0){
        #pragma unroll
        for (int i = tid; i < BM*4; i += 256){
            int m = i >> 2, c = i & 3;
            uint32_t d = aBase + (uint32_t)(st*(BM*BK*2) + (m*BK + ((c ^ ((m>>1)&3))<<3))*2);
            cp16(d, Ag + (long)m*lda + k0 + c*8);
        }
        #pragma unroll
        for (int i = tid; i < BK*BCH; i += 256){
            int k = i / BCH, c = i % BCH;
            uint32_t d = bBase + (uint32_t)(st*(BK*BN*2) + (k*BN + ((c ^ (k&7))<<3))*2);
            cp16(d, Bg + (long)(k0+k)*ldb + c*8);
        }
    };

    const int KT = K / BK;
    load_stage(0, 0);
    asm volatile("cp.async.commit_group;");
    for (int kt = 0; kt < KT; kt++){
        const int st = kt & 1;
        if (kt + 1 < KT){
            load_stage(st^1, (kt+1)*BK);
            asm volatile("cp.async.commit_group;");
            asm volatile("cp.async.wait_group 1;");
        } else {
            asm volatile("cp.async.wait_group 0;");
        }
        __syncthreads();
        const uint32_t aSt = aBase + st*(BM*BK*2);
        const uint32_t bSt = bBase + st*(BK*BN*2);
        #pragma unroll
        for (int ks = 0; ks < 2; ks++){
            uint32_t af[MT][4], bfr[NT2][4];
            #pragma unroll
            for (int mi = 0; mi < MT; mi++){
                int row = wm*WM + mi*16 + r8 + ((quad&1)<<3);
                int kc  = ks*2 + (quad>>1);
                uint32_t ad = aSt + (uint32_t)((row*BK + (((kc ^ ((row>>1)&3)))<<3))*2);
                ldsm4(af[mi], ad);
            }
            #pragma unroll
            for (int nj = 0; nj < NT2; nj++){
                int rk  = ks*16 + r8 + ((quad&1)<<3);
                int col = wn*WN + nj*16 + ((quad>>1)<<3);
                uint32_t bd = bSt + (uint32_t)((rk*BN + (((col>>3) ^ (rk&7))<<3))*2);
                ldsm4t(bfr[nj], bd);
            }
            #pragma unroll
            for (int mi = 0; mi < MT; mi++)
                #pragma unroll
                for (int nj = 0; nj < NT2; nj++){
                    mma_bf16(acc[mi][2*nj],   af[mi], bfr[nj]);
                    mma_bf16(acc[mi][2*nj+1], af[mi], bfr[nj]+2);
                }
        }
        __syncthreads();
    }

    const int tg = lane >> 2, tq = lane & 3;
    #pragma unroll
    for (int mi = 0; mi < MT; mi++){
        long r0 = (long)blockIdx.y*BM + wm*WM + mi*16 + tg;
        #pragma unroll
        for (int ni = 0; ni < NT; ni++){
            int c = blockIdx.x*BN + wn*WN + ni*8 + 2*tq;
            C[ r0   *ldc + c    ] = acc[mi][ni][0];
            C[ r0   *ldc + c + 1] = acc[mi][ni][1];
            C[(r0+8)*ldc + c    ] = acc[mi][ni][2];
            C[(r0+8)*ldc + c + 1] = acc[mi][ni][3];
        }
    }
}

// ---------------- tf32 GEMM (tiny K=32 dt projection) ----------------
template<int EPI>
__global__ void tf32gemm_k(const float* __restrict__ A, const float* __restrict__ B,
                           float* __restrict__ C, int K, int lda, int ldb, int ldc,
                           const float* __restrict__ bias){
    constexpr int BM = 128, BN = 64, BK = 16;
    constexpr int ASTR = BK + 4;
    constexpr int BSTR = BN + 8;
    __shared__ uint32_t As[BM*ASTR];
    __shared__ uint32_t Bs[BK*BSTR];

    const int tid  = threadIdx.x;
    const int wid  = tid >> 5, lane = tid & 31;
    const int wm   = wid >> 1, wn = wid & 1;
    const int m0   = wm*32, n0 = wn*32;
    const int tg   = lane >> 2, kq = lane & 3;

    float acc[2][4][4];
    #pragma unroll
    for (int mi=0;mi<2;mi++)
        #pragma unroll
        for (int ni=0;ni<4;ni++)
            #pragma unroll
            for (int r=0;r<4;r++) acc[mi][ni][r]=0.f;

    const float* Ab = A + (long)blockIdx.y * BM * lda;
    const float* Bb = B + blockIdx.x * BN;

    for (int k0 = 0; k0 < K; k0 += BK){
        #pragma unroll
        for (int i = tid; i < BM*BK/4; i += 256){
            int r = i >> 2, c4 = i & 3;
            float4 v = *reinterpret_cast<const float4*>(Ab + (long)r*lda + k0 + c4*4);
            uint4 w = make_uint4(f2tf(v.x), f2tf(v.y), f2tf(v.z), f2tf(v.w));
            *reinterpret_cast<uint4*>(&As[r*ASTR + c4*4]) = w;
        }
        #pragma unroll
        for (int i = tid; i < BK*BN/4; i += 256){
            int r = i >> 4, c4 = i & 15;
            float4 v = *reinterpret_cast<const float4*>(Bb + (long)(k0+r)*ldb + c4*4);
            uint4 w = make_uint4(f2tf(v.x), f2tf(v.y), f2tf(v.z), f2tf(v.w));
            *reinterpret_cast<uint4*>(&Bs[r*BSTR + c4*4]) = w;
        }
        __syncthreads();
        #pragma unroll
        for (int kk = 0; kk < BK; kk += 8){
            uint32_t af[2][4], bf[4][2];
            #pragma unroll
            for (int mi=0; mi<2; mi++){
                int mr = m0 + mi*16;
                af[mi][0] = As[(mr + tg    )*ASTR + kk + kq    ];
                af[mi][1] = As[(mr + 8 + tg)*ASTR + kk + kq    ];
                af[mi][2] = As[(mr + tg    )*ASTR + kk + 4 + kq];
                af[mi][3] = As[(mr + 8 + tg)*ASTR + kk + 4 + kq];
            }
            #pragma unroll
            for (int ni=0; ni<4; ni++){
                int nc = n0 + ni*8 + tg;
                bf[ni][0] = Bs[(kk + kq    )*BSTR + nc];
                bf[ni][1] = Bs[(kk + 4 + kq)*BSTR + nc];
            }
            #pragma unroll
            for (int mi=0; mi<2; mi++)
                #pragma unroll
                for (int ni=0; ni<4; ni++)
                    mma_tf32(acc[mi][ni], af[mi], bf[ni]);
        }
        __syncthreads();
    }
    #pragma unroll
    for (int mi=0; mi<2; mi++){
        long r0 = (long)blockIdx.y*BM + m0 + mi*16 + tg;
        #pragma unroll
        for (int ni=0; ni<4; ni++){
            int c = blockIdx.x*BN + n0 + ni*8 + 2*kq;
            float v0 = acc[mi][ni][0], v1 = acc[mi][ni][1];
            float v2 = acc[mi][ni][2], v3 = acc[mi][ni][3];
            if (EPI == 1){
                v0 = softplusf(v0 + bias[c]);   v1 = softplusf(v1 + bias[c+1]);
                v2 = softplusf(v2 + bias[c]);   v3 = softplusf(v3 + bias[c+1]);
            }
            C[ r0   *ldc + c    ] = v0;
            C[ r0   *ldc + c + 1] = v1;
            C[(r0+8)*ldc + c    ] = v2;
            C[(r0+8)*ldc + c + 1] = v3;
        }
    }
}

// ---------------- conv: rolling-window, 16 timesteps per block ----------------
__global__ void conv_kernel(const float* __restrict__ xz,
                            const float* __restrict__ conv_w,
                            const float* __restrict__ conv_b,
                            float* __restrict__ u,
                            __nv_bfloat16* __restrict__ ub){
    const int b = blockIdx.y, l0 = blockIdx.x*16;
    const int d = threadIdx.x * 4;
    float4 w0 = *reinterpret_cast<const float4*>(conv_w + 0*DIN + d);
    float4 w1 = *reinterpret_cast<const float4*>(conv_w + 1*DIN + d);
    float4 w2 = *reinterpret_cast<const float4*>(conv_w + 2*DIN + d);
    float4 w3 = *reinterpret_cast<const float4*>(conv_w + 3*DIN + d);
    float4 bv = *reinterpret_cast<const float4*>(conv_b + d);
    float4 x0, x1, x2;
    if (l0 > 0){
        x0 = *reinterpret_cast<const float4*>(xz + ((long)(b*L_)+l0-3)*(2*DIN) + d);
        x1 = *reinterpret_cast<const float4*>(xz + ((long)(b*L_)+l0-2)*(2*DIN) + d);
        x2 = *reinterpret_cast<const float4*>(xz + ((long)(b*L_)+l0-1)*(2*DIN) + d);
    } else {
        x0 = make_float4(0,0,0,0); x1 = x0; x2 = x0;
    }
    #pragma unroll
    for (int tt = 0; tt < 16; tt++){
        long row = (long)(b*L_) + l0 + tt;
        float4 x3 = *reinterpret_cast<const float4*>(xz + row*(2*DIN) + d);
        float4 a = bv;
        a.x = fmaf(w0.x,x0.x, fmaf(w1.x,x1.x, fmaf(w2.x,x2.x, fmaf(w3.x,x3.x, a.x))));
        a.y = fmaf(w0.y,x0.y, fmaf(w1.y,x1.y, fmaf(w2.y,x2.y, fmaf(w3.y,x3.y, a.y))));
        a.z = fmaf(w0.z,x0.z, fmaf(w1.z,x1.z, fmaf(w2.z,x2.z, fmaf(w3.z,x3.z, a.z))));
        a.w = fmaf(w0.w,x0.w, fmaf(w1.w,x1.w, fmaf(w2.w,x2.w, fmaf(w3.w,x3.w, a.w))));
        float4 o;
        o.x = a.x / (1.f + __expf(-a.x));
        o.y = a.y / (1.f + __expf(-a.y));
        o.z = a.z / (1.f + __expf(-a.z));
        o.w = a.w / (1.f + __expf(-a.w));
        *reinterpret_cast<float4*>(u + row*DIN + d) = o;
        *(__nv_bfloat162*)(ub + row*DIN + d)     = __floats2bfloat162_rn(o.x, o.y);
        *(__nv_bfloat162*)(ub + row*DIN + d + 2) = __floats2bfloat162_rn(o.z, o.w);
        x0 = x1; x1 = x2; x2 = x3;
    }
}

// ---------------- chunked scan: pass A (local scans, chunks 0..6) ----------------
__global__ void scanA_kernel(const float* __restrict__ dbc,
                             const float* __restrict__ dt,
                             const float* __restrict__ u,
                             const float* __restrict__ A_log,
                             float* __restrict__ hend,
                             float* __restrict__ Ssum){
    const int b = blockIdx.x, c = blockIdx.z;
    const int d = blockIdx.y * 128 + threadIdx.x;
    const int t0 = c * CHK;
    float h[DSTATE], An[DSTATE];
    #pragma unroll
    for (int n = 0; n < DSTATE; n++){
        h[n]  = 0.f;
        An[n] = -expf(A_log[d*DSTATE + n]);
    }
    __shared__ float sB[CHK][DSTATE];
    for (int i = threadIdx.x; i < CHK*DSTATE; i += 128){
        int tt = i >> 4, j = i & 15;
        sB[tt][j] = dbc[((long)(b*L_) + (t0+tt))*64 + DTRANK + j];
    }
    __syncthreads();
    float S = 0.f;
    for (int tt = 0; tt < CHK; tt++){
        long row = (long)(b*L_) + t0 + tt;
        float dtv = dt[row*DIN + d];
        float uv  = u [row*DIN + d];
        float dtu = dtv * uv;
        S += dtv;
        #pragma unroll
        for (int n = 0; n < DSTATE; n++)
            h[n] = fmaf(__expf(dtv * An[n]), h[n], dtu * sB[tt][n]);
    }
    #pragma unroll
    for (int n = 0; n < DSTATE; n++)
        hend[((long)(b*NCH + c)*DSTATE + n)*DIN + d] = h[n];
    Ssum[(long)(b*NCH + c)*DIN + d] = S;
}

// ---------------- chunked scan: pass B (combine -> h_in for chunks 6,7) ----------
__global__ void scanB_kernel(const float* __restrict__ A_log,
                             const float* __restrict__ hend,
                             const float* __restrict__ Ssum,
                             float* __restrict__ hin){
    const int b = blockIdx.x;
    const int d = blockIdx.y * 128 + threadIdx.x;
    float h[DSTATE], An[DSTATE];
    #pragma unroll
    for (int n = 0; n < DSTATE; n++){
        h[n]  = 0.f;
        An[n] = -expf(A_log[d*DSTATE + n]);
    }
    for (int c = 0; c < 7; c++){
        if (c == 6){
            #pragma unroll
            for (int n = 0; n < DSTATE; n++)
                hin[((long)(0*B_ + b)*DSTATE + n)*DIN + d] = h[n];
        }
        float S = Ssum[(long)(b*NCH + c)*DIN + d];
        #pragma unroll
        for (int n = 0; n < DSTATE; n++)
            h[n] = fmaf(__expf(An[n]*S), h[n],
                        hend[((long)(b*NCH + c)*DSTATE + n)*DIN + d]);
    }
    #pragma unroll
    for (int n = 0; n < DSTATE; n++)
        hin[((long)(1*B_ + b)*DSTATE + n)*DIN + d] = h[n];
}

// ---------------- chunked scan: pass C (rescan chunks 6,7, emit gated y) --------
__global__ void scanC_kernel(const float* __restrict__ dbc,
                             const float* __restrict__ dt,
                             const float* __restrict__ u,
                             const float* __restrict__ xz,
                             const float* __restrict__ A_log,
                             const float* __restrict__ Dp,
                             const float* __restrict__ hin,
                             __nv_bfloat16* __restrict__ yg){
    const int b = blockIdx.x, ci = blockIdx.z;   // ci: 0->chunk6, 1->chunk7
    const int d = blockIdx.y * 128 + threadIdx.x;
    const int t0 = (6 + ci) * CHK;
    float h[DSTATE], An[DSTATE];
    #pragma unroll
    for (int n = 0; n < DSTATE; n++){
        h[n]  = hin[((long)(ci*B_ + b)*DSTATE + n)*DIN + d];
        An[n] = -expf(A_log[d*DSTATE + n]);
    }
    const float Dv = Dp[d];
    __shared__ float sB[CHK][DSTATE];
    __shared__ float sC[CHK][DSTATE];
    for (int i = threadIdx.x; i < CHK*2*DSTATE; i += 128){
        int tt = i >> 5, j = i & 31;
        float v = dbc[((long)(b*L_) + (t0+tt))*64 + DTRANK + j];
        if (j < DSTATE) sB[tt][j] = v; else sC[tt][j-DSTATE] = v;
    }
    __syncthreads();
    for (int tt = 0; tt < CHK; tt++){
        int t = t0 + tt;
        long row = (long)(b*L_) + t;
        float dtv = dt[row*DIN + d];
        float uv  = u [row*DIN + d];
        float dtu = dtv * uv;
        float y = 0.f;
        #pragma unroll
        for (int n = 0; n < DSTATE; n++){
            h[n] = fmaf(__expf(dtv * An[n]), h[n], dtu * sB[tt][n]);
            y = fmaf(h[n], sC[tt][n], y);
        }
        if (t >= L_ - PRED){
            float zv = xz[row*(2*DIN) + DIN + d];
            float sg = 1.f / (1.f + __expf(-zv));
            yg[((long)(b*PRED) + (t - (L_-PRED)))*DIN + d] =
                __float2bfloat16((y + uv*Dv) * (zv * sg));
        }
    }
}

// ---------------- head: warp-per-row GEMV + denorm ----------------
__global__ void head_kernel(const float* __restrict__ x2,
                            const float* __restrict__ W_head,
                            const float* __restrict__ mean,
                            const float* __restrict__ stdv,
                            float* __restrict__ out){
    __shared__ float sw[DM*COUT];
    for (int i = threadIdx.x; i < DM*COUT; i += 256)
        sw[i] = W_head[i];
    __syncthreads();
    int warp = threadIdx.x >> 5, lane = threadIdx.x & 31;
    int m = blockIdx.x*8 + warp;                 // grid 192
    float acc[COUT] = {};
    for (int k = lane; k < DM; k += 32){
        float xv = x2[(long)m*DM + k];
        #pragma unroll
        for (int c = 0; c < COUT; c++)
            acc[c] = fmaf(xv, sw[k*COUT + c], acc[c]);
    }
    #pragma unroll
    for (int c = 0; c < COUT; c++)
        #pragma unroll
        for (int o = 16; o > 0; o >>= 1)
            acc[c] += __shfl_xor_sync(0xffffffffu, acc[c], o);
    if (lane == 0){
        int b = m / PRED;
        #pragma unroll
        for (int c = 0; c < COUT; c++)
            out[(long)m*COUT + c] = acc[c] * stdv[b*ENC + c] + mean[b*ENC + c];
    }
}

// ---------------- launcher ----------------
extern "C" void kernel_launch(void* const* d_in, const int* in_sizes, int n_in,
                              void* d_out, int out_size){
    const float* x_enc  = (const float*)d_in[0];
    const float* W_emb  = (const float*)d_in[1];
    const float* W_in   = (const float*)d_in[2];
    const float* conv_w = (const float*)d_in[3];
    const float* conv_b = (const float*)d_in[4];
    const float* W_xproj= (const float*)d_in[5];
    const float* W_dt   = (const float*)d_in[6];
    const float* b_dt   = (const float*)d_in[7];
    const float* A_log  = (const float*)d_in[8];
    const float* Dp     = (const float*)d_in[9];
    const float* W_out  = (const float*)d_in[10];
    const float* W_head = (const float*)d_in[11];
    float* out = (float*)d_out;

    float *p_mean,*p_std,*p_pos,*p_xz,*p_u,*p_dbc,*p_dt,*p_x2,*p_hend,*p_S,*p_hin;
    __nv_bfloat16 *p_xb,*p_ub,*p_ygb,*p_winb,*p_wxpb,*p_woutb;
    cudaGetSymbolAddress((void**)&p_mean, g_mean);
    cudaGetSymbolAddress((void**)&p_std,  g_std);
    cudaGetSymbolAddress((void**)&p_pos,  g_pos);
    cudaGetSymbolAddress((void**)&p_xb,   g_xb);
    cudaGetSymbolAddress((void**)&p_xz,   g_xz);
    cudaGetSymbolAddress((void**)&p_u,    g_u);
    cudaGetSymbolAddress((void**)&p_ub,   g_ub);
    cudaGetSymbolAddress((void**)&p_dbc,  g_dbc);
    cudaGetSymbolAddress((void**)&p_dt,   g_dt);
    cudaGetSymbolAddress((void**)&p_hend, g_hend);
    cudaGetSymbolAddress((void**)&p_S,    g_S);
    cudaGetSymbolAddress((void**)&p_hin,  g_hin);
    cudaGetSymbolAddress((void**)&p_ygb,  g_ygb);
    cudaGetSymbolAddress((void**)&p_x2,   g_x2);
    cudaGetSymbolAddress((void**)&p_winb, g_winb);
    cudaGetSymbolAddress((void**)&p_wxpb, g_wxpb);
    cudaGetSymbolAddress((void**)&p_woutb,g_woutb);

    // 0) weights fp32 -> bf16 ; positional table
    cvt3_kernel<<<(DM*2*DIN)/(256*4), 256>>>(W_in, p_winb, W_xproj, p_wxpb, W_out, p_woutb);
    pos_kernel<<<L_, 256>>>(p_pos);

    // 1) per-(b,c) stats
    meanstd_kernel<<<B_*ENC, 32>>>(x_enc, p_mean, p_std);

    // 2) normalize + 3-tap token embed + pos table -> g_xb (bf16)
    embed_kernel<<<dim3(L_, B_), 256>>>(x_enc, W_emb, p_mean, p_std, p_pos, p_xb);

    // 3) xz = x @ W_in  (8192x512 @ 512x2048) -- bf16 mma
    bf16gemm_k<128,128,64,32><<<dim3((2*DIN)/128, NTOK/128), 256>>>(
        p_xb, p_winb, p_xz, DM, DM, 2*DIN, 2*DIN);

    // 4) depthwise causal conv + silu -> g_u (fp32) + g_ub (bf16)
    conv_kernel<<<dim3(L_/16, B_), 256>>>(p_xz, conv_w, conv_b, p_u, p_ub);

    // 5) dbc = u @ W_xproj  (8192x1024 @ 1024x64) -- bf16, BM=64 for occupancy
    bf16gemm_k<64,64,16,32><<<dim3(1, NTOK/64), 256>>>(
        p_ub, p_wxpb, p_dbc, DIN, DIN, 64, 64);

    // 6) dt = softplus(dbc[:, :32] @ W_dt + b_dt) -- tf32
    tf32gemm_k<1><<<dim3(DIN/64, NTOK/128), 256>>>(
        p_dbc, W_dt, p_dt, DTRANK, 64, DIN, DIN, b_dt);

    // 7) chunked selective scan
    scanA_kernel<<<dim3(B_, DIN/128, 7), 128>>>(p_dbc, p_dt, p_u, A_log, p_hend, p_S);
    scanB_kernel<<<dim3(B_, DIN/128), 128>>>(A_log, p_hend, p_S, p_hin);
    scanC_kernel<<<dim3(B_, DIN/128, 2), 128>>>(p_dbc, p_dt, p_u, p_xz, A_log, Dp, p_hin, p_ygb);

    // 8) x2 = yg @ W_out  (1536x1024 @ 1024x512) -- bf16, BM=64
    bf16gemm_k<64,64,16,32><<<dim3(DM/64, MOUT/64), 256>>>(
        p_ygb, p_woutb, p_x2, DIN, DIN, DM, DM);

    // 9) out = (x2 @ W_head) * std + mean
    head_kernel<<<MOUT/8, 256>>>(p_x2, W_head, p_mean, p_std, out);
}

// round 6
// speedup vs baseline: 3.4364x; 1.1034x over previous
#include <cuda_runtime.h>
#include <cuda_bf16.h>
#include <math.h>
#include <stdint.h>

// ---------------- problem dims ----------------
#define B_   16
#define L_   512
#define ENC  7
#define DM   512
#define DIN  1024
#define DSTATE 16
#define DCONV 4
#define DTRANK 32
#define COUT 7
#define PRED 96
#define NTOK (B_*L_)          // 8192
#define MOUT (B_*PRED)        // 1536
#define NCH  8
#define CHK  64

// ---------------- scratch (device globals; allocation-free) ----------------
__device__ float g_mean[B_*ENC];
__device__ float g_std[B_*ENC];
__device__ float g_pos[L_*DM];
__device__ __nv_bfloat16 g_xb [NTOK*DM];
__device__ float g_xz [NTOK*2*DIN];
__device__ float g_u  [NTOK*DIN];
__device__ __nv_bfloat16 g_ub [NTOK*DIN];
__device__ float g_dbc[NTOK*(DTRANK+2*DSTATE)];
__device__ float g_dt [NTOK*DIN];
__device__ float g_hend[B_*NCH*DSTATE*DIN];
__device__ float g_S   [B_*NCH*DIN];
__device__ float g_hin [2*B_*DSTATE*DIN];
__device__ __nv_bfloat16 g_ygb[MOUT*DIN];
__device__ float g_x2 [MOUT*DM];
__device__ __nv_bfloat16 g_winb [DM*2*DIN];
__device__ __nv_bfloat16 g_wxpb [DIN*(DTRANK+2*DSTATE)];
__device__ __nv_bfloat16 g_woutb[DIN*DM];

// ---------------- helpers ----------------
__device__ __forceinline__ float softplusf(float x){
    return x > 20.f ? x : log1pf(expf(x));
}
__device__ __forceinline__ uint32_t f2tf(float x){
    uint32_t r; asm("cvt.rna.tf32.f32 %0, %1;" : "=r"(r) : "f"(x)); return r;
}
__device__ __forceinline__ void mma_tf32(float* c, const uint32_t* a, const uint32_t* b){
    asm volatile(
      "mma.sync.aligned.m16n8k8.row.col.f32.tf32.tf32.f32 "
      "{%0,%1,%2,%3}, {%4,%5,%6,%7}, {%8,%9}, {%0,%1,%2,%3};\n"
      : "+f"(c[0]), "+f"(c[1]), "+f"(c[2]), "+f"(c[3])
      : "r"(a[0]), "r"(a[1]), "r"(a[2]), "r"(a[3]), "r"(b[0]), "r"(b[1]));
}
__device__ __forceinline__ void mma_bf16(float* c, const uint32_t* a, const uint32_t* b){
    asm volatile(
      "mma.sync.aligned.m16n8k16.row.col.f32.bf16.bf16.f32 "
      "{%0,%1,%2,%3}, {%4,%5,%6,%7}, {%8,%9}, {%0,%1,%2,%3};\n"
      : "+f"(c[0]), "+f"(c[1]), "+f"(c[2]), "+f"(c[3])
      : "r"(a[0]), "r"(a[1]), "r"(a[2]), "r"(a[3]), "r"(b[0]), "r"(b[1]));
}
__device__ __forceinline__ void ldsm4(uint32_t* r, uint32_t addr){
    asm volatile("ldmatrix.sync.aligned.m8n8.x4.shared.b16 {%0,%1,%2,%3}, [%4];"
        : "=r"(r[0]), "=r"(r[1]), "=r"(r[2]), "=r"(r[3]) : "r"(addr));
}
__device__ __forceinline__ void ldsm4t(uint32_t* r, uint32_t addr){
    asm volatile("ldmatrix.sync.aligned.m8n8.x4.trans.shared.b16 {%0,%1,%2,%3}, [%4];"
        : "=r"(r[0]), "=r"(r[1]), "=r"(r[2]), "=r"(r[3]) : "r"(addr));
}
__device__ __forceinline__ void cp16(uint32_t dst, const void* src){
    asm volatile("cp.async.cg.shared.global [%0], [%1], 16;" :: "r"(dst), "l"(src));
}

// ---------------- prep: weight cvt (blocks 0..1023) + pos table (1024..1535) -----
__global__ void prep_kernel(const float* __restrict__ a, __nv_bfloat16* __restrict__ ab,
                            const float* __restrict__ b, __nv_bfloat16* __restrict__ bb,
                            const float* __restrict__ c, __nv_bfloat16* __restrict__ cb,
                            float* __restrict__ pos){
    int bid = blockIdx.x;
    if (bid < 1024){
        int i = (bid*256 + threadIdx.x)*4;
        if (i < DM*2*DIN){
            float4 v = *(const float4*)(a+i);
            *(__nv_bfloat162*)(ab+i)   = __floats2bfloat162_rn(v.x, v.y);
            *(__nv_bfloat162*)(ab+i+2) = __floats2bfloat162_rn(v.z, v.w);
        }
        if (i < DIN*64){
            float4 v = *(const float4*)(b+i);
            *(__nv_bfloat162*)(bb+i)   = __floats2bfloat162_rn(v.x, v.y);
            *(__nv_bfloat162*)(bb+i+2) = __floats2bfloat162_rn(v.z, v.w);
        }
        if (i < DIN*DM){
            float4 v = *(const float4*)(c+i);
            *(__nv_bfloat162*)(cb+i)   = __floats2bfloat162_rn(v.x, v.y);
            *(__nv_bfloat162*)(cb+i+2) = __floats2bfloat162_rn(v.z, v.w);
        }
    } else {
        int l = bid - 1024;
        const float NEG_LN1E4_OVER_D = -9.210340371976184f / (float)DM;
        for (int d = threadIdx.x; d < DM; d += 256){
            float freq = expf((float)(2*(d>>1)) * NEG_LN1E4_OVER_D);
            float ang  = (float)l * freq;
            pos[l*DM + d] = (d & 1) ? cosf(ang) : sinf(ang);
        }
    }
}

// ---------------- kernel 1: per-(b,c) mean/std over L ----------------
__global__ void meanstd_kernel(const float* __restrict__ x_enc,
                               float* __restrict__ mean, float* __restrict__ stdv){
    int b = blockIdx.x / ENC, c = blockIdx.x % ENC;
    float s = 0.f, s2 = 0.f;
    for (int l = threadIdx.x; l < L_; l += 32){
        float v = x_enc[(b*L_ + l)*ENC + c];
        s += v; s2 += v*v;
    }
    #pragma unroll
    for (int o = 16; o > 0; o >>= 1){
        s  += __shfl_xor_sync(0xffffffffu, s,  o);
        s2 += __shfl_xor_sync(0xffffffffu, s2, o);
    }
    if (threadIdx.x == 0){
        float m = s * (1.f/L_);
        float var = s2 * (1.f/L_) - m*m;
        mean[blockIdx.x] = m;
        stdv[blockIdx.x] = sqrtf(var + 1e-5f);
    }
}

// ---------------- embed: 8 l's per block, W_emb taps in registers ----------------
__global__ __launch_bounds__(256) void embed_kernel(
        const float* __restrict__ x_enc,
        const float* __restrict__ W_emb,
        const float* __restrict__ mean,
        const float* __restrict__ stdv,
        const float* __restrict__ pos,
        __nv_bfloat16* __restrict__ xout){
    const int l0 = blockIdx.x*8, b = blockIdx.y;
    const int tid = threadIdx.x;
    const int d0 = tid*2;
    __shared__ float s[10][ENC];           // rows l0-1 .. l0+8 (wrap)
    if (tid < 10*ENC){
        int r = tid / ENC, c = tid % ENC;
        int lm = (l0 - 1 + r + L_) & (L_-1);
        s[r][c] = (x_enc[(b*L_ + lm)*ENC + c] - mean[b*ENC + c]) / stdv[b*ENC + c];
    }
    float w0[3][ENC], w1[3][ENC];
    #pragma unroll
    for (int k = 0; k < 3; k++)
        #pragma unroll
        for (int c = 0; c < ENC; c++){
            float2 wv = *reinterpret_cast<const float2*>(W_emb + (k*ENC + c)*DM + d0);
            w0[k][c] = wv.x; w1[k][c] = wv.y;
        }
    __syncthreads();
    #pragma unroll
    for (int i = 0; i < 8; i++){
        int l = l0 + i;
        float2 pv = *reinterpret_cast<const float2*>(pos + l*DM + d0);
        float a0 = pv.x, a1 = pv.y;
        #pragma unroll
        for (int k = 0; k < 3; k++)
            #pragma unroll
            for (int c = 0; c < ENC; c++){
                float sv = s[i+k][c];
                a0 = fmaf(sv, w0[k][c], a0);
                a1 = fmaf(sv, w1[k][c], a1);
            }
        *(__nv_bfloat162*)(xout + ((long)(b*L_) + l)*DM + d0) = __floats2bfloat162_rn(a0, a1);
    }
}

// ---------------- bf16 tensor-core GEMM, 3-stage cp.async pipeline ----------------
template<int BM, int BN, int WM, int WN>
__global__ __launch_bounds__(256) void bf16gemm_k(
    const __nv_bfloat16* __restrict__ A, const __nv_bfloat16* __restrict__ B,
    float* __restrict__ C, int K, int lda, int ldb, int ldc)
{
    constexpr int BK = 32, STG = 3;
    constexpr int WARPS_N = BN/WN;
    constexpr int MT = WM/16, NT = WN/8, NT2 = WN/16;
    constexpr int BCH = BN/8;
    __shared__ __nv_bfloat16 As[STG][BM*BK];
    __shared__ __nv_bfloat16 Bs[STG][BK*BN];

    const int tid = threadIdx.x, lane = tid & 31, wid = tid >> 5;
    const int wm = wid / WARPS_N, wn = wid % WARPS_N;
    const int quad = lane >> 3, r8 = lane & 7;
    const uint32_t aBase = (uint32_t)__cvta_generic_to_shared(&As[0][0]);
    const uint32_t bBase = (uint32_t)__cvta_generic_to_shared(&Bs[0][0]);

    const __nv_bfloat16* Ag = A + (long)blockIdx.y * BM * lda;
    const __nv_bfloat16* Bg = B + blockIdx.x * BN;

    float acc[MT][NT][4] = {};

    auto load_stage = [&](int st, int k0){
        #pragma unroll
        for (int i = tid; i < BM*4; i += 256){
            int m = i >> 2, c = i & 3;
            uint32_t d = aBase + (uint32_t)(st*(BM*BK*2) + (m*BK + ((c ^ ((m>>1)&3))<<3))*2);
            cp16(d, Ag + (long)m*lda + k0 + c*8);
        }
        #pragma unroll
        for (int i = tid; i < BK*BCH; i += 256){
            int k = i / BCH, c = i % BCH;
            uint32_t d = bBase + (uint32_t)(st*(BK*BN*2) + (k*BN + ((c ^ (k&7))<<3))*2);
            cp16(d, Bg + (long)(k0+k)*ldb + c*8);
        }
    };

    const int KT = K / BK;
    load_stage(0, 0);
    asm volatile("cp.async.commit_group;");
    load_stage(1, BK);
    asm volatile("cp.async.commit_group;");

    for (int kt = 0; kt < KT; kt++){
        if (kt + 1 < KT) asm volatile("cp.async.wait_group 1;");
        else             asm volatile("cp.async.wait_group 0;");
        __syncthreads();
        if (kt + 2 < KT){
            load_stage((kt+2)%STG, (kt+2)*BK);
            asm volatile("cp.async.commit_group;");
        }
        const int st = kt % STG;
        const uint32_t aSt = aBase + st*(BM*BK*2);
        const uint32_t bSt = bBase + st*(BK*BN*2);
        #pragma unroll
        for (int ks = 0; ks < 2; ks++){
            uint32_t af[MT][4], bfr[NT2][4];
            #pragma unroll
            for (int mi = 0; mi < MT; mi++){
                int row = wm*WM + mi*16 + r8 + ((quad&1)<<3);
                int kc  = ks*2 + (quad>>1);
                uint32_t ad = aSt + (uint32_t)((row*BK + (((kc ^ ((row>>1)&3)))<<3))*2);
                ldsm4(af[mi], ad);
            }
            #pragma unroll
            for (int nj = 0; nj < NT2; nj++){
                int rk  = ks*16 + r8 + ((quad&1)<<3);
                int col = wn*WN + nj*16 + ((quad>>1)<<3);
                uint32_t bd = bSt + (uint32_t)((rk*BN + (((col>>3) ^ (rk&7))<<3))*2);
                ldsm4t(bfr[nj], bd);
            }
            #pragma unroll
            for (int mi = 0; mi < MT; mi++)
                #pragma unroll
                for (int nj = 0; nj < NT2; nj++){
                    mma_bf16(acc[mi][2*nj],   af[mi], bfr[nj]);
                    mma_bf16(acc[mi][2*nj+1], af[mi], bfr[nj]+2);
                }
        }
    }

    const int tg = lane >> 2, tq = lane & 3;
    #pragma unroll
    for (int mi = 0; mi < MT; mi++){
        long r0 = (long)blockIdx.y*BM + wm*WM + mi*16 + tg;
        #pragma unroll
        for (int ni = 0; ni < NT; ni++){
            int c = blockIdx.x*BN + wn*WN + ni*8 + 2*tq;
            *reinterpret_cast<float2*>(&C[ r0   *ldc + c]) = make_float2(acc[mi][ni][0], acc[mi][ni][1]);
            *reinterpret_cast<float2*>(&C[(r0+8)*ldc + c]) = make_float2(acc[mi][ni][2], acc[mi][ni][3]);
        }
    }
}

// ---------------- tf32 GEMM (tiny K=32 dt projection) ----------------
template<int EPI>
__global__ void tf32gemm_k(const float* __restrict__ A, const float* __restrict__ B,
                           float* __restrict__ C, int K, int lda, int ldb, int ldc,
                           const float* __restrict__ bias){
    constexpr int BM = 128, BN = 64, BK = 16;
    constexpr int ASTR = BK + 4;
    constexpr int BSTR = BN + 8;
    __shared__ uint32_t As[BM*ASTR];
    __shared__ uint32_t Bs[BK*BSTR];

    const int tid  = threadIdx.x;
    const int wid  = tid >> 5, lane = tid & 31;
    const int wm   = wid >> 1, wn = wid & 1;
    const int m0   = wm*32, n0 = wn*32;
    const int tg   = lane >> 2, kq = lane & 3;

    float acc[2][4][4];
    #pragma unroll
    for (int mi=0;mi<2;mi++)
        #pragma unroll
        for (int ni=0;ni<4;ni++)
            #pragma unroll
            for (int r=0;r<4;r++) acc[mi][ni][r]=0.f;

    const float* Ab = A + (long)blockIdx.y * BM * lda;
    const float* Bb = B + blockIdx.x * BN;

    for (int k0 = 0; k0 < K; k0 += BK){
        #pragma unroll
        for (int i = tid; i < BM*BK/4; i += 256){
            int r = i >> 2, c4 = i & 3;
            float4 v = *reinterpret_cast<const float4*>(Ab + (long)r*lda + k0 + c4*4);
            uint4 w = make_uint4(f2tf(v.x), f2tf(v.y), f2tf(v.z), f2tf(v.w));
            *reinterpret_cast<uint4*>(&As[r*ASTR + c4*4]) = w;
        }
        #pragma unroll
        for (int i = tid; i < BK*BN/4; i += 256){
            int r = i >> 4, c4 = i & 15;
            float4 v = *reinterpret_cast<const float4*>(Bb + (long)(k0+r)*ldb + c4*4);
            uint4 w = make_uint4(f2tf(v.x), f2tf(v.y), f2tf(v.z), f2tf(v.w));
            *reinterpret_cast<uint4*>(&Bs[r*BSTR + c4*4]) = w;
        }
        __syncthreads();
        #pragma unroll
        for (int kk = 0; kk < BK; kk += 8){
            uint32_t af[2][4], bf[4][2];
            #pragma unroll
            for (int mi=0; mi<2; mi++){
                int mr = m0 + mi*16;
                af[mi][0] = As[(mr + tg    )*ASTR + kk + kq    ];
                af[mi][1] = As[(mr + 8 + tg)*ASTR + kk + kq    ];
                af[mi][2] = As[(mr + tg    )*ASTR + kk + 4 + kq];
                af[mi][3] = As[(mr + 8 + tg)*ASTR + kk + 4 + kq];
            }
            #pragma unroll
            for (int ni=0; ni<4; ni++){
                int nc = n0 + ni*8 + tg;
                bf[ni][0] = Bs[(kk + kq    )*BSTR + nc];
                bf[ni][1] = Bs[(kk + 4 + kq)*BSTR + nc];
            }
            #pragma unroll
            for (int mi=0; mi<2; mi++)
                #pragma unroll
                for (int ni=0; ni<4; ni++)
                    mma_tf32(acc[mi][ni], af[mi], bf[ni]);
        }
        __syncthreads();
    }
    #pragma unroll
    for (int mi=0; mi<2; mi++){
        long r0 = (long)blockIdx.y*BM + m0 + mi*16 + tg;
        #pragma unroll
        for (int ni=0; ni<4; ni++){
            int c = blockIdx.x*BN + n0 + ni*8 + 2*kq;
            float v0 = acc[mi][ni][0], v1 = acc[mi][ni][1];
            float v2 = acc[mi][ni][2], v3 = acc[mi][ni][3];
            if (EPI == 1){
                v0 = softplusf(v0 + bias[c]);   v1 = softplusf(v1 + bias[c+1]);
                v2 = softplusf(v2 + bias[c]);   v3 = softplusf(v3 + bias[c+1]);
            }
            *reinterpret_cast<float2*>(&C[ r0   *ldc + c]) = make_float2(v0, v1);
            *reinterpret_cast<float2*>(&C[(r0+8)*ldc + c]) = make_float2(v2, v3);
        }
    }
}

// ---------------- conv: rolling-window, 16 timesteps per block ----------------
__global__ void conv_kernel(const float* __restrict__ xz,
                            const float* __restrict__ conv_w,
                            const float* __restrict__ conv_b,
                            float* __restrict__ u,
                            __nv_bfloat16* __restrict__ ub){
    const int b = blockIdx.y, l0 = blockIdx.x*16;
    const int d = threadIdx.x * 4;
    float4 w0 = *reinterpret_cast<const float4*>(conv_w + 0*DIN + d);
    float4 w1 = *reinterpret_cast<const float4*>(conv_w + 1*DIN + d);
    float4 w2 = *reinterpret_cast<const float4*>(conv_w + 2*DIN + d);
    float4 w3 = *reinterpret_cast<const float4*>(conv_w + 3*DIN + d);
    float4 bv = *reinterpret_cast<const float4*>(conv_b + d);
    float4 x0, x1, x2;
    if (l0 > 0){
        x0 = *reinterpret_cast<const float4*>(xz + ((long)(b*L_)+l0-3)*(2*DIN) + d);
        x1 = *reinterpret_cast<const float4*>(xz + ((long)(b*L_)+l0-2)*(2*DIN) + d);
        x2 = *reinterpret_cast<const float4*>(xz + ((long)(b*L_)+l0-1)*(2*DIN) + d);
    } else {
        x0 = make_float4(0,0,0,0); x1 = x0; x2 = x0;
    }
    #pragma unroll
    for (int tt = 0; tt < 16; tt++){
        long row = (long)(b*L_) + l0 + tt;
        float4 x3 = *reinterpret_cast<const float4*>(xz + row*(2*DIN) + d);
        float4 a = bv;
        a.x = fmaf(w0.x,x0.x, fmaf(w1.x,x1.x, fmaf(w2.x,x2.x, fmaf(w3.x,x3.x, a.x))));
        a.y = fmaf(w0.y,x0.y, fmaf(w1.y,x1.y, fmaf(w2.y,x2.y, fmaf(w3.y,x3.y, a.y))));
        a.z = fmaf(w0.z,x0.z, fmaf(w1.z,x1.z, fmaf(w2.z,x2.z, fmaf(w3.z,x3.z, a.z))));
        a.w = fmaf(w0.w,x0.w, fmaf(w1.w,x1.w, fmaf(w2.w,x2.w, fmaf(w3.w,x3.w, a.w))));
        float4 o;
        o.x = a.x / (1.f + __expf(-a.x));
        o.y = a.y / (1.f + __expf(-a.y));
        o.z = a.z / (1.f + __expf(-a.z));
        o.w = a.w / (1.f + __expf(-a.w));
        *reinterpret_cast<float4*>(u + row*DIN + d) = o;
        *(__nv_bfloat162*)(ub + row*DIN + d)     = __floats2bfloat162_rn(o.x, o.y);
        *(__nv_bfloat162*)(ub + row*DIN + d + 2) = __floats2bfloat162_rn(o.z, o.w);
        x0 = x1; x1 = x2; x2 = x3;
    }
}

// ---------------- chunked scan: pass A (local scans, chunks 0..6) ----------------
__global__ void scanA_kernel(const float* __restrict__ dbc,
                             const float* __restrict__ dt,
                             const float* __restrict__ u,
                             const float* __restrict__ A_log,
                             float* __restrict__ hend,
                             float* __restrict__ Ssum){
    const int b = blockIdx.x, c = blockIdx.z;
    const int d = blockIdx.y * 128 + threadIdx.x;
    const int t0 = c * CHK;
    float h[DSTATE], An[DSTATE];
    #pragma unroll
    for (int n = 0; n < DSTATE; n++){
        h[n]  = 0.f;
        An[n] = -expf(A_log[d*DSTATE + n]);
    }
    __shared__ float sB[CHK][DSTATE];
    for (int i = threadIdx.x; i < CHK*DSTATE; i += 128){
        int tt = i >> 4, j = i & 15;
        sB[tt][j] = dbc[((long)(b*L_) + (t0+tt))*64 + DTRANK + j];
    }
    __syncthreads();
    float S = 0.f;
    for (int tt = 0; tt < CHK; tt++){
        long row = (long)(b*L_) + t0 + tt;
        float dtv = dt[row*DIN + d];
        float uv  = u [row*DIN + d];
        float dtu = dtv * uv;
        S += dtv;
        #pragma unroll
        for (int n = 0; n < DSTATE; n++)
            h[n] = fmaf(__expf(dtv * An[n]), h[n], dtu * sB[tt][n]);
    }
    #pragma unroll
    for (int n = 0; n < DSTATE; n++)
        hend[((long)(b*NCH + c)*DSTATE + n)*DIN + d] = h[n];
    Ssum[(long)(b*NCH + c)*DIN + d] = S;
}

// ---------------- chunked scan: pass B ----------------
__global__ void scanB_kernel(const float* __restrict__ A_log,
                             const float* __restrict__ hend,
                             const float* __restrict__ Ssum,
                             float* __restrict__ hin){
    const int b = blockIdx.x;
    const int d = blockIdx.y * 128 + threadIdx.x;
    float h[DSTATE], An[DSTATE];
    #pragma unroll
    for (int n = 0; n < DSTATE; n++){
        h[n]  = 0.f;
        An[n] = -expf(A_log[d*DSTATE + n]);
    }
    for (int c = 0; c < 7; c++){
        if (c == 6){
            #pragma unroll
            for (int n = 0; n < DSTATE; n++)
                hin[((long)(0*B_ + b)*DSTATE + n)*DIN + d] = h[n];
        }
        float S = Ssum[(long)(b*NCH + c)*DIN + d];
        #pragma unroll
        for (int n = 0; n < DSTATE; n++)
            h[n] = fmaf(__expf(An[n]*S), h[n],
                        hend[((long)(b*NCH + c)*DSTATE + n)*DIN + d]);
    }
    #pragma unroll
    for (int n = 0; n < DSTATE; n++)
        hin[((long)(1*B_ + b)*DSTATE + n)*DIN + d] = h[n];
}

// ---------------- chunked scan: pass C ----------------
__global__ void scanC_kernel(const float* __restrict__ dbc,
                             const float* __restrict__ dt,
                             const float* __restrict__ u,
                             const float* __restrict__ xz,
                             const float* __restrict__ A_log,
                             const float* __restrict__ Dp,
                             const float* __restrict__ hin,
                             __nv_bfloat16* __restrict__ yg){
    const int b = blockIdx.x, ci = blockIdx.z;
    const int d = blockIdx.y * 128 + threadIdx.x;
    const int t0 = (6 + ci) * CHK;
    float h[DSTATE], An[DSTATE];
    #pragma unroll
    for (int n = 0; n < DSTATE; n++){
        h[n]  = hin[((long)(ci*B_ + b)*DSTATE + n)*DIN + d];
        An[n] = -expf(A_log[d*DSTATE + n]);
    }
    const float Dv = Dp[d];
    __shared__ float sB[CHK][DSTATE];
    __shared__ float sC[CHK][DSTATE];
    for (int i = threadIdx.x; i < CHK*2*DSTATE; i += 128){
        int tt = i >> 5, j = i & 31;
        float v = dbc[((long)(b*L_) + (t0+tt))*64 + DTRANK + j];
        if (j < DSTATE) sB[tt][j] = v; else sC[tt][j-DSTATE] = v;
    }
    __syncthreads();
    for (int tt = 0; tt < CHK; tt++){
        int t = t0 + tt;
        long row = (long)(b*L_) + t;
        float dtv = dt[row*DIN + d];
        float uv  = u [row*DIN + d];
        float dtu = dtv * uv;
        float y = 0.f;
        #pragma unroll
        for (int n = 0; n < DSTATE; n++){
            h[n] = fmaf(__expf(dtv * An[n]), h[n], dtu * sB[tt][n]);
            y = fmaf(h[n], sC[tt][n], y);
        }
        if (t >= L_ - PRED){
            float zv = xz[row*(2*DIN) + DIN + d];
            float sg = 1.f / (1.f + __expf(-zv));
            yg[((long)(b*PRED) + (t - (L_-PRED)))*DIN + d] =
                __float2bfloat16((y + uv*Dv) * (zv * sg));
        }
    }
}

// ---------------- head: warp-per-row GEMV + denorm ----------------
__global__ void head_kernel(const float* __restrict__ x2,
                            const float* __restrict__ W_head,
                            const float* __restrict__ mean,
                            const float* __restrict__ stdv,
                            float* __restrict__ out){
    __shared__ float sw[DM*COUT];
    for (int i = threadIdx.x; i < DM*COUT; i += 256)
        sw[i] = W_head[i];
    __syncthreads();
    int warp = threadIdx.x >> 5, lane = threadIdx.x & 31;
    int m = blockIdx.x*8 + warp;
    float acc[COUT] = {};
    for (int k = lane; k < DM; k += 32){
        float xv = x2[(long)m*DM + k];
        #pragma unroll
        for (int c = 0; c < COUT; c++)
            acc[c] = fmaf(xv, sw[k*COUT + c], acc[c]);
    }
    #pragma unroll
    for (int c = 0; c < COUT; c++)
        #pragma unroll
        for (int o = 16; o > 0; o >>= 1)
            acc[c] += __shfl_xor_sync(0xffffffffu, acc[c], o);
    if (lane == 0){
        int b = m / PRED;
        #pragma unroll
        for (int c = 0; c < COUT; c++)
            out[(long)m*COUT + c] = acc[c] * stdv[b*ENC + c] + mean[b*ENC + c];
    }
}

// ---------------- launcher ----------------
extern "C" void kernel_launch(void* const* d_in, const int* in_sizes, int n_in,
                              void* d_out, int out_size){
    const float* x_enc  = (const float*)d_in[0];
    const float* W_emb  = (const float*)d_in[1];
    const float* W_in   = (const float*)d_in[2];
    const float* conv_w = (const float*)d_in[3];
    const float* conv_b = (const float*)d_in[4];
    const float* W_xproj= (const float*)d_in[5];
    const float* W_dt   = (const float*)d_in[6];
    const float* b_dt   = (const float*)d_in[7];
    const float* A_log  = (const float*)d_in[8];
    const float* Dp     = (const float*)d_in[9];
    const float* W_out  = (const float*)d_in[10];
    const float* W_head = (const float*)d_in[11];
    float* out = (float*)d_out;

    float *p_mean,*p_std,*p_pos,*p_xz,*p_u,*p_dbc,*p_dt,*p_x2,*p_hend,*p_S,*p_hin;
    __nv_bfloat16 *p_xb,*p_ub,*p_ygb,*p_winb,*p_wxpb,*p_woutb;
    cudaGetSymbolAddress((void**)&p_mean, g_mean);
    cudaGetSymbolAddress((void**)&p_std,  g_std);
    cudaGetSymbolAddress((void**)&p_pos,  g_pos);
    cudaGetSymbolAddress((void**)&p_xb,   g_xb);
    cudaGetSymbolAddress((void**)&p_xz,   g_xz);
    cudaGetSymbolAddress((void**)&p_u,    g_u);
    cudaGetSymbolAddress((void**)&p_ub,   g_ub);
    cudaGetSymbolAddress((void**)&p_dbc,  g_dbc);
    cudaGetSymbolAddress((void**)&p_dt,   g_dt);
    cudaGetSymbolAddress((void**)&p_hend, g_hend);
    cudaGetSymbolAddress((void**)&p_S,    g_S);
    cudaGetSymbolAddress((void**)&p_hin,  g_hin);
    cudaGetSymbolAddress((void**)&p_ygb,  g_ygb);
    cudaGetSymbolAddress((void**)&p_x2,   g_x2);
    cudaGetSymbolAddress((void**)&p_winb, g_winb);
    cudaGetSymbolAddress((void**)&p_wxpb, g_wxpb);
    cudaGetSymbolAddress((void**)&p_woutb,g_woutb);

    // 0) weights fp32 -> bf16 + positional table (merged)
    prep_kernel<<<1536, 256>>>(W_in, p_winb, W_xproj, p_wxpb, W_out, p_woutb, p_pos);

    // 1) per-(b,c) stats
    meanstd_kernel<<<B_*ENC, 32>>>(x_enc, p_mean, p_std);

    // 2) normalize + 3-tap token embed + pos -> g_xb (bf16)
    embed_kernel<<<dim3(L_/8, B_), 256>>>(x_enc, W_emb, p_mean, p_std, p_pos, p_xb);

    // 3) xz = x @ W_in  (8192x512 @ 512x2048) -- bf16 mma, 3-stage
    bf16gemm_k<128,128,64,32><<<dim3((2*DIN)/128, NTOK/128), 256>>>(
        p_xb, p_winb, p_xz, DM, DM, 2*DIN, 2*DIN);

    // 4) depthwise causal conv + silu -> g_u (fp32) + g_ub (bf16)
    conv_kernel<<<dim3(L_/16, B_), 256>>>(p_xz, conv_w, conv_b, p_u, p_ub);

    // 5) dbc = u @ W_xproj  (8192x1024 @ 1024x64) -- bf16, BM=64
    bf16gemm_k<64,64,16,32><<<dim3(1, NTOK/64), 256>>>(
        p_ub, p_wxpb, p_dbc, DIN, DIN, 64, 64);

    // 6) dt = softplus(dbc[:, :32] @ W_dt + b_dt) -- tf32
    tf32gemm_k<1><<<dim3(DIN/64, NTOK/128), 256>>>(
        p_dbc, W_dt, p_dt, DTRANK, 64, DIN, DIN, b_dt);

    // 7) chunked selective scan
    scanA_kernel<<<dim3(B_, DIN/128, 7), 128>>>(p_dbc, p_dt, p_u, A_log, p_hend, p_S);
    scanB_kernel<<<dim3(B_, DIN/128), 128>>>(A_log, p_hend, p_S, p_hin);
    scanC_kernel<<<dim3(B_, DIN/128, 2), 128>>>(p_dbc, p_dt, p_u, p_xz, A_log, Dp, p_hin, p_ygb);

    // 8) x2 = yg @ W_out  (1536x1024 @ 1024x512) -- bf16, BM=64
    bf16gemm_k<64,64,16,32><<<dim3(DM/64, MOUT/64), 256>>>(
        p_ygb, p_woutb, p_x2, DIN, DIN, DM, DM);

    // 9) out = (x2 @ W_head) * std + mean
    head_kernel<<<MOUT/8, 256>>>(p_x2, W_head, p_mean, p_std, out);
}

// round 8
// speedup vs baseline: 3.7547x; 1.0926x over previous
#include <cuda_runtime.h>
#include <cuda_bf16.h>
#include <math.h>
#include <stdint.h>

// ---------------- problem dims ----------------
#define B_   16
#define L_   512
#define ENC  7
#define DM   512
#define DIN  1024
#define DSTATE 16
#define DCONV 4
#define DTRANK 32
#define COUT 7
#define PRED 96
#define NTOK (B_*L_)          // 8192
#define MOUT (B_*PRED)        // 1536
#define NCH  8
#define CHK  64

// ---------------- scratch (device globals; allocation-free) ----------------
__device__ float g_mean[B_*ENC];
__device__ float g_std[B_*ENC];
__device__ float g_pos[L_*DM];
__device__ __nv_bfloat16 g_xb [NTOK*DM];      // embedded input (bf16)
__device__ float g_xm [NTOK*DIN];             // x @ W_in[:, :DIN]
__device__ float g_zg [MOUT*DIN];             // z for last 96 steps (compact)
__device__ float g_u  [NTOK*DIN];             // silu(conv(xm)) fp32
__device__ __nv_bfloat16 g_ub [NTOK*DIN];     // bf16 copy for GEMM
__device__ float g_dbc[NTOK*(DTRANK+2*DSTATE)];
__device__ float g_hend[B_*NCH*DSTATE*DIN];
__device__ float g_S   [B_*NCH*DIN];
__device__ float g_hin [2*B_*DSTATE*DIN];
__device__ __nv_bfloat16 g_ygb[MOUT*DIN];
__device__ float g_x2 [MOUT*DM];
__device__ __nv_bfloat16 g_winb [DM*2*DIN];
__device__ __nv_bfloat16 g_wxpb [DIN*(DTRANK+2*DSTATE)];
__device__ __nv_bfloat16 g_woutb[DIN*DM];

// ---------------- helpers ----------------
__device__ __forceinline__ float softplusf(float x){
    return x > 20.f ? x : log1pf(expf(x));
}
__device__ __forceinline__ void mma_bf16(float* c, const uint32_t* a, const uint32_t* b){
    asm volatile(
      "mma.sync.aligned.m16n8k16.row.col.f32.bf16.bf16.f32 "
      "{%0,%1,%2,%3}, {%4,%5,%6,%7}, {%8,%9}, {%0,%1,%2,%3};\n"
      : "+f"(c[0]), "+f"(c[1]), "+f"(c[2]), "+f"(c[3])
      : "r"(a[0]), "r"(a[1]), "r"(a[2]), "r"(a[3]), "r"(b[0]), "r"(b[1]));
}
__device__ __forceinline__ void ldsm4(uint32_t* r, uint32_t addr){
    asm volatile("ldmatrix.sync.aligned.m8n8.x4.shared.b16 {%0,%1,%2,%3}, [%4];"
        : "=r"(r[0]), "=r"(r[1]), "=r"(r[2]), "=r"(r[3]) : "r"(addr));
}
__device__ __forceinline__ void ldsm4t(uint32_t* r, uint32_t addr){
    asm volatile("ldmatrix.sync.aligned.m8n8.x4.trans.shared.b16 {%0,%1,%2,%3}, [%4];"
        : "=r"(r[0]), "=r"(r[1]), "=r"(r[2]), "=r"(r[3]) : "r"(addr));
}
__device__ __forceinline__ void cp16(uint32_t dst, const void* src){
    asm volatile("cp.async.cg.shared.global [%0], [%1], 16;" :: "r"(dst), "l"(src));
}

// ---------------- prep: weight cvt (blocks 0..1023) + pos table (1024..1535) -----
__global__ void prep_kernel(const float* __restrict__ a, __nv_bfloat16* __restrict__ ab,
                            const float* __restrict__ b, __nv_bfloat16* __restrict__ bb,
                            const float* __restrict__ c, __nv_bfloat16* __restrict__ cb,
                            float* __restrict__ pos){
    int bid = blockIdx.x;
    if (bid < 1024){
        int i = (bid*256 + threadIdx.x)*4;
        if (i < DM*2*DIN){
            float4 v = *(const float4*)(a+i);
            *(__nv_bfloat162*)(ab+i)   = __floats2bfloat162_rn(v.x, v.y);
            *(__nv_bfloat162*)(ab+i+2) = __floats2bfloat162_rn(v.z, v.w);
        }
        if (i < DIN*64){
            float4 v = *(const float4*)(b+i);
            *(__nv_bfloat162*)(bb+i)   = __floats2bfloat162_rn(v.x, v.y);
            *(__nv_bfloat162*)(bb+i+2) = __floats2bfloat162_rn(v.z, v.w);
        }
        if (i < DIN*DM){
            float4 v = *(const float4*)(c+i);
            *(__nv_bfloat162*)(cb+i)   = __floats2bfloat162_rn(v.x, v.y);
            *(__nv_bfloat162*)(cb+i+2) = __floats2bfloat162_rn(v.z, v.w);
        }
    } else {
        int l = bid - 1024;
        const float NEG_LN1E4_OVER_D = -9.210340371976184f / (float)DM;
        for (int d = threadIdx.x; d < DM; d += 256){
            float freq = expf((float)(2*(d>>1)) * NEG_LN1E4_OVER_D);
            float ang  = (float)l * freq;
            pos[l*DM + d] = (d & 1) ? cosf(ang) : sinf(ang);
        }
    }
}

// ---------------- kernel 1: per-(b,c) mean/std over L ----------------
__global__ void meanstd_kernel(const float* __restrict__ x_enc,
                               float* __restrict__ mean, float* __restrict__ stdv){
    int b = blockIdx.x / ENC, c = blockIdx.x % ENC;
    float s = 0.f, s2 = 0.f;
    for (int l = threadIdx.x; l < L_; l += 32){
        float v = x_enc[(b*L_ + l)*ENC + c];
        s += v; s2 += v*v;
    }
    #pragma unroll
    for (int o = 16; o > 0; o >>= 1){
        s  += __shfl_xor_sync(0xffffffffu, s,  o);
        s2 += __shfl_xor_sync(0xffffffffu, s2, o);
    }
    if (threadIdx.x == 0){
        float m = s * (1.f/L_);
        float var = s2 * (1.f/L_) - m*m;
        mean[blockIdx.x] = m;
        stdv[blockIdx.x] = sqrtf(var + 1e-5f);
    }
}

// ---------------- embed: 8 l's per block, W_emb taps in registers ----------------
__global__ __launch_bounds__(256) void embed_kernel(
        const float* __restrict__ x_enc,
        const float* __restrict__ W_emb,
        const float* __restrict__ mean,
        const float* __restrict__ stdv,
        const float* __restrict__ pos,
        __nv_bfloat16* __restrict__ xout){
    const int l0 = blockIdx.x*8, b = blockIdx.y;
    const int tid = threadIdx.x;
    const int d0 = tid*2;
    __shared__ float s[10][ENC];
    if (tid < 10*ENC){
        int r = tid / ENC, c = tid % ENC;
        int lm = (l0 - 1 + r + L_) & (L_-1);
        s[r][c] = (x_enc[(b*L_ + lm)*ENC + c] - mean[b*ENC + c]) / stdv[b*ENC + c];
    }
    float w0[3][ENC], w1[3][ENC];
    #pragma unroll
    for (int k = 0; k < 3; k++)
        #pragma unroll
        for (int c = 0; c < ENC; c++){
            float2 wv = *reinterpret_cast<const float2*>(W_emb + (k*ENC + c)*DM + d0);
            w0[k][c] = wv.x; w1[k][c] = wv.y;
        }
    __syncthreads();
    #pragma unroll
    for (int i = 0; i < 8; i++){
        int l = l0 + i;
        float2 pv = *reinterpret_cast<const float2*>(pos + l*DM + d0);
        float a0 = pv.x, a1 = pv.y;
        #pragma unroll
        for (int k = 0; k < 3; k++)
            #pragma unroll
            for (int c = 0; c < ENC; c++){
                float sv = s[i+k][c];
                a0 = fmaf(sv, w0[k][c], a0);
                a1 = fmaf(sv, w1[k][c], a1);
            }
        *(__nv_bfloat162*)(xout + ((long)(b*L_) + l)*DM + d0) = __floats2bfloat162_rn(a0, a1);
    }
}

// ---------------- bf16 tensor-core GEMM, 3-stage cp.async pipeline ----------------
// REMAP=1: A row gm maps to global row (gm/PRED)*L_ + (L_-PRED) + gm%PRED
template<int BM, int BN, int WM, int WN, int REMAP>
__global__ __launch_bounds__(256) void bf16gemm_k(
    const __nv_bfloat16* __restrict__ A, const __nv_bfloat16* __restrict__ B,
    float* __restrict__ C, int K, int lda, int ldb, int ldc)
{
    constexpr int BK = 32, STG = 3;
    constexpr int WARPS_N = BN/WN;
    constexpr int MT = WM/16, NT = WN/8, NT2 = WN/16;
    constexpr int BCH = BN/8;
    __shared__ __nv_bfloat16 As[STG][BM*BK];
    __shared__ __nv_bfloat16 Bs[STG][BK*BN];

    const int tid = threadIdx.x, lane = tid & 31, wid = tid >> 5;
    const int wm = wid / WARPS_N, wn = wid % WARPS_N;
    const int quad = lane >> 3, r8 = lane & 7;
    const uint32_t aBase = (uint32_t)__cvta_generic_to_shared(&As[0][0]);
    const uint32_t bBase = (uint32_t)__cvta_generic_to_shared(&Bs[0][0]);

    const __nv_bfloat16* Ag = A + (long)blockIdx.y * BM * lda;
    const __nv_bfloat16* Bg = B + blockIdx.x * BN;

    float acc[MT][NT][4] = {};

    auto load_stage = [&](int st, int k0){
        #pragma unroll
        for (int i = tid; i < BM*4; i += 256){
            int m = i >> 2, c = i & 3;
            uint32_t d = aBase + (uint32_t)(st*(BM*BK*2) + (m*BK + ((c ^ ((m>>1)&3))<<3))*2);
            const __nv_bfloat16* asrc;
            if (REMAP){
                int gm = blockIdx.y*BM + m;
                long grow = (long)(gm/PRED)*L_ + (L_-PRED) + (gm%PRED);
                asrc = A + grow*lda + k0 + c*8;
            } else {
                asrc = Ag + (long)m*lda + k0 + c*8;
            }
            cp16(d, asrc);
        }
        #pragma unroll
        for (int i = tid; i < BK*BCH; i += 256){
            int k = i / BCH, c = i % BCH;
            uint32_t d = bBase + (uint32_t)(st*(BK*BN*2) + (k*BN + ((c ^ (k&7))<<3))*2);
            cp16(d, Bg + (long)(k0+k)*ldb + c*8);
        }
    };

    const int KT = K / BK;
    load_stage(0, 0);
    asm volatile("cp.async.commit_group;");
    load_stage(1, BK);
    asm volatile("cp.async.commit_group;");

    for (int kt = 0; kt < KT; kt++){
        if (kt + 1 < KT) asm volatile("cp.async.wait_group 1;");
        else             asm volatile("cp.async.wait_group 0;");
        __syncthreads();
        if (kt + 2 < KT){
            load_stage((kt+2)%STG, (kt+2)*BK);
            asm volatile("cp.async.commit_group;");
        }
        const int st = kt % STG;
        const uint32_t aSt = aBase + st*(BM*BK*2);
        const uint32_t bSt = bBase + st*(BK*BN*2);
        #pragma unroll
        for (int ks = 0; ks < 2; ks++){
            uint32_t af[MT][4], bfr[NT2][4];
            #pragma unroll
            for (int mi = 0; mi < MT; mi++){
                int row = wm*WM + mi*16 + r8 + ((quad&1)<<3);
                int kc  = ks*2 + (quad>>1);
                uint32_t ad = aSt + (uint32_t)((row*BK + (((kc ^ ((row>>1)&3)))<<3))*2);
                ldsm4(af[mi], ad);
            }
            #pragma unroll
            for (int nj = 0; nj < NT2; nj++){
                int rk  = ks*16 + r8 + ((quad&1)<<3);
                int col = wn*WN + nj*16 + ((quad>>1)<<3);
                uint32_t bd = bSt + (uint32_t)((rk*BN + (((col>>3) ^ (rk&7))<<3))*2);
                ldsm4t(bfr[nj], bd);
            }
            #pragma unroll
            for (int mi = 0; mi < MT; mi++)
                #pragma unroll
                for (int nj = 0; nj < NT2; nj++){
                    mma_bf16(acc[mi][2*nj],   af[mi], bfr[nj]);
                    mma_bf16(acc[mi][2*nj+1], af[mi], bfr[nj]+2);
                }
        }
    }

    const int tg = lane >> 2, tq = lane & 3;
    #pragma unroll
    for (int mi = 0; mi < MT; mi++){
        long r0 = (long)blockIdx.y*BM + wm*WM + mi*16 + tg;
        #pragma unroll
        for (int ni = 0; ni < NT; ni++){
            int c = blockIdx.x*BN + wn*WN + ni*8 + 2*tq;
            *reinterpret_cast<float2*>(&C[ r0   *ldc + c]) = make_float2(acc[mi][ni][0], acc[mi][ni][1]);
            *reinterpret_cast<float2*>(&C[(r0+8)*ldc + c]) = make_float2(acc[mi][ni][2], acc[mi][ni][3]);
        }
    }
}

// ---------------- conv: rolling-window over xm (stride DIN) ----------------
__global__ void conv_kernel(const float* __restrict__ xm,
                            const float* __restrict__ conv_w,
                            const float* __restrict__ conv_b,
                            float* __restrict__ u,
                            __nv_bfloat16* __restrict__ ub){
    const int b = blockIdx.y, l0 = blockIdx.x*16;
    const int d = threadIdx.x * 4;
    float4 w0 = *reinterpret_cast<const float4*>(conv_w + 0*DIN + d);
    float4 w1 = *reinterpret_cast<const float4*>(conv_w + 1*DIN + d);
    float4 w2 = *reinterpret_cast<const float4*>(conv_w + 2*DIN + d);
    float4 w3 = *reinterpret_cast<const float4*>(conv_w + 3*DIN + d);
    float4 bv = *reinterpret_cast<const float4*>(conv_b + d);
    float4 x0, x1, x2;
    if (l0 > 0){
        x0 = *reinterpret_cast<const float4*>(xm + ((long)(b*L_)+l0-3)*DIN + d);
        x1 = *reinterpret_cast<const float4*>(xm + ((long)(b*L_)+l0-2)*DIN + d);
        x2 = *reinterpret_cast<const float4*>(xm + ((long)(b*L_)+l0-1)*DIN + d);
    } else {
        x0 = make_float4(0,0,0,0); x1 = x0; x2 = x0;
    }
    #pragma unroll
    for (int tt = 0; tt < 16; tt++){
        long row = (long)(b*L_) + l0 + tt;
        float4 x3 = *reinterpret_cast<const float4*>(xm + row*DIN + d);
        float4 a = bv;
        a.x = fmaf(w0.x,x0.x, fmaf(w1.x,x1.x, fmaf(w2.x,x2.x, fmaf(w3.x,x3.x, a.x))));
        a.y = fmaf(w0.y,x0.y, fmaf(w1.y,x1.y, fmaf(w2.y,x2.y, fmaf(w3.y,x3.y, a.y))));
        a.z = fmaf(w0.z,x0.z, fmaf(w1.z,x1.z, fmaf(w2.z,x2.z, fmaf(w3.z,x3.z, a.z))));
        a.w = fmaf(w0.w,x0.w, fmaf(w1.w,x1.w, fmaf(w2.w,x2.w, fmaf(w3.w,x3.w, a.w))));
        float4 o;
        o.x = a.x / (1.f + __expf(-a.x));
        o.y = a.y / (1.f + __expf(-a.y));
        o.z = a.z / (1.f + __expf(-a.z));
        o.w = a.w / (1.f + __expf(-a.w));
        *reinterpret_cast<float4*>(u + row*DIN + d) = o;
        *(__nv_bfloat162*)(ub + row*DIN + d)     = __floats2bfloat162_rn(o.x, o.y);
        *(__nv_bfloat162*)(ub + row*DIN + d + 2) = __floats2bfloat162_rn(o.z, o.w);
        x0 = x1; x1 = x2; x2 = x3;
    }
}

// ---------------- scan A: local scans chunks 0..6, dt fused ----------------
__global__ void scanA_kernel(const float* __restrict__ dbc,
                             const float* __restrict__ u,
                             const float* __restrict__ A_log,
                             const float* __restrict__ W_dt,
                             const float* __restrict__ b_dt,
                             float* __restrict__ hend,
                             float* __restrict__ Ssum){
    const int b = blockIdx.x, c = blockIdx.z;
    const int d = blockIdx.y * 128 + threadIdx.x;
    const int t0 = c * CHK;
    float h[DSTATE], An[DSTATE], wdt[DTRANK];
    #pragma unroll
    for (int n = 0; n < DSTATE; n++){
        h[n]  = 0.f;
        An[n] = -expf(A_log[d*DSTATE + n]);
    }
    #pragma unroll
    for (int k = 0; k < DTRANK; k++)
        wdt[k] = W_dt[k*DIN + d];
    const float bdt = b_dt[d];
    __shared__ float sRow[CHK][64];                 // full dbc rows
    for (int i = threadIdx.x; i < CHK*16; i += 128){
        int tt = i >> 4, c4 = i & 15;
        *reinterpret_cast<float4*>(&sRow[tt][c4*4]) =
            *reinterpret_cast<const float4*>(dbc + ((long)(b*L_) + (t0+tt))*64 + c4*4);
    }
    __syncthreads();
    float S = 0.f;
    for (int tt = 0; tt < CHK; tt++){
        float dot = bdt;
        #pragma unroll
        for (int k = 0; k < DTRANK; k++)
            dot = fmaf(sRow[tt][k], wdt[k], dot);
        float dtv = softplusf(dot);
        float uv  = u[((long)(b*L_) + t0 + tt)*DIN + d];
        float dtu = dtv * uv;
        S += dtv;
        #pragma unroll
        for (int n = 0; n < DSTATE; n++)
            h[n] = fmaf(__expf(dtv * An[n]), h[n], dtu * sRow[tt][DTRANK + n]);
    }
    #pragma unroll
    for (int n = 0; n < DSTATE; n++)
        hend[((long)(b*NCH + c)*DSTATE + n)*DIN + d] = h[n];
    Ssum[(long)(b*NCH + c)*DIN + d] = S;
}

// ---------------- scan B: combine -> h_in for chunks 6,7 ----------------
__global__ void scanB_kernel(const float* __restrict__ A_log,
                             const float* __restrict__ hend,
                             const float* __restrict__ Ssum,
                             float* __restrict__ hin){
    const int b = blockIdx.x;
    const int d = blockIdx.y * 128 + threadIdx.x;
    float h[DSTATE], An[DSTATE];
    #pragma unroll
    for (int n = 0; n < DSTATE; n++){
        h[n]  = 0.f;
        An[n] = -expf(A_log[d*DSTATE + n]);
    }
    for (int c = 0; c < 7; c++){
        if (c == 6){
            #pragma unroll
            for (int n = 0; n < DSTATE; n++)
                hin[((long)(0*B_ + b)*DSTATE + n)*DIN + d] = h[n];
        }
        float S = Ssum[(long)(b*NCH + c)*DIN + d];
        #pragma unroll
        for (int n = 0; n < DSTATE; n++)
            h[n] = fmaf(__expf(An[n]*S), h[n],
                        hend[((long)(b*NCH + c)*DSTATE + n)*DIN + d]);
    }
    #pragma unroll
    for (int n = 0; n < DSTATE; n++)
        hin[((long)(1*B_ + b)*DSTATE + n)*DIN + d] = h[n];
}

// ---------------- scan C: rescan chunks 6,7 with dt fused, emit gated y --------
__global__ void scanC_kernel(const float* __restrict__ dbc,
                             const float* __restrict__ u,
                             const float* __restrict__ zg,
                             const float* __restrict__ A_log,
                             const float* __restrict__ W_dt,
                             const float* __restrict__ b_dt,
                             const float* __restrict__ Dp,
                             const float* __restrict__ hin,
                             __nv_bfloat16* __restrict__ yg){
    const int b = blockIdx.x, ci = blockIdx.z;
    const int d = blockIdx.y * 128 + threadIdx.x;
    const int t0 = (6 + ci) * CHK;
    float h[DSTATE], An[DSTATE], wdt[DTRANK];
    #pragma unroll
    for (int n = 0; n < DSTATE; n++){
        h[n]  = hin[((long)(ci*B_ + b)*DSTATE + n)*DIN + d];
        An[n] = -expf(A_log[d*DSTATE + n]);
    }
    #pragma unroll
    for (int k = 0; k < DTRANK; k++)
        wdt[k] = W_dt[k*DIN + d];
    const float bdt = b_dt[d];
    const float Dv = Dp[d];
    __shared__ float sRow[CHK][64];
    for (int i = threadIdx.x; i < CHK*16; i += 128){
        int tt = i >> 4, c4 = i & 15;
        *reinterpret_cast<float4*>(&sRow[tt][c4*4]) =
            *reinterpret_cast<const float4*>(dbc + ((long)(b*L_) + (t0+tt))*64 + c4*4);
    }
    __syncthreads();
    for (int tt = 0; tt < CHK; tt++){
        int t = t0 + tt;
        long row = (long)(b*L_) + t;
        float dot = bdt;
        #pragma unroll
        for (int k = 0; k < DTRANK; k++)
            dot = fmaf(sRow[tt][k], wdt[k], dot);
        float dtv = softplusf(dot);
        float uv  = u[row*DIN + d];
        float dtu = dtv * uv;
        float y = 0.f;
        #pragma unroll
        for (int n = 0; n < DSTATE; n++){
            h[n] = fmaf(__expf(dtv * An[n]), h[n], dtu * sRow[tt][DTRANK + n]);
            y = fmaf(h[n], sRow[tt][DTRANK + DSTATE + n], y);
        }
        if (t >= L_ - PRED){
            long orow = (long)(b*PRED) + (t - (L_-PRED));
            float zv = zg[orow*DIN + d];
            float sg = 1.f / (1.f + __expf(-zv));
            yg[orow*DIN + d] = __float2bfloat16((y + uv*Dv) * (zv * sg));
        }
    }
}

// ---------------- head: warp-per-row GEMV + denorm ----------------
__global__ void head_kernel(const float* __restrict__ x2,
                            const float* __restrict__ W_head,
                            const float* __restrict__ mean,
                            const float* __restrict__ stdv,
                            float* __restrict__ out){
    __shared__ float sw[DM*COUT];
    for (int i = threadIdx.x; i < DM*COUT; i += 256)
        sw[i] = W_head[i];
    __syncthreads();
    int warp = threadIdx.x >> 5, lane = threadIdx.x & 31;
    int m = blockIdx.x*8 + warp;
    float acc[COUT] = {};
    for (int k = lane; k < DM; k += 32){
        float xv = x2[(long)m*DM + k];
        #pragma unroll
        for (int c = 0; c < COUT; c++)
            acc[c] = fmaf(xv, sw[k*COUT + c], acc[c]);
    }
    #pragma unroll
    for (int c = 0; c < COUT; c++)
        #pragma unroll
        for (int o = 16; o > 0; o >>= 1)
            acc[c] += __shfl_xor_sync(0xffffffffu, acc[c], o);
    if (lane == 0){
        int b = m / PRED;
        #pragma unroll
        for (int c = 0; c < COUT; c++)
            out[(long)m*COUT + c] = acc[c] * stdv[b*ENC + c] + mean[b*ENC + c];
    }
}

// ---------------- launcher ----------------
extern "C" void kernel_launch(void* const* d_in, const int* in_sizes, int n_in,
                              void* d_out, int out_size){
    const float* x_enc  = (const float*)d_in[0];
    const float* W_emb  = (const float*)d_in[1];
    const float* W_in   = (const float*)d_in[2];
    const float* conv_w = (const float*)d_in[3];
    const float* conv_b = (const float*)d_in[4];
    const float* W_xproj= (const float*)d_in[5];
    const float* W_dt   = (const float*)d_in[6];
    const float* b_dt   = (const float*)d_in[7];
    const float* A_log  = (const float*)d_in[8];
    const float* Dp     = (const float*)d_in[9];
    const float* W_out  = (const float*)d_in[10];
    const float* W_head = (const float*)d_in[11];
    float* out = (float*)d_out;

    float *p_mean,*p_std,*p_pos,*p_xm,*p_zg,*p_u,*p_dbc,*p_x2,*p_hend,*p_S,*p_hin;
    __nv_bfloat16 *p_xb,*p_ub,*p_ygb,*p_winb,*p_wxpb,*p_woutb;
    cudaGetSymbolAddress((void**)&p_mean, g_mean);
    cudaGetSymbolAddress((void**)&p_std,  g_std);
    cudaGetSymbolAddress((void**)&p_pos,  g_pos);
    cudaGetSymbolAddress((void**)&p_xb,   g_xb);
    cudaGetSymbolAddress((void**)&p_xm,   g_xm);
    cudaGetSymbolAddress((void**)&p_zg,   g_zg);
    cudaGetSymbolAddress((void**)&p_u,    g_u);
    cudaGetSymbolAddress((void**)&p_ub,   g_ub);
    cudaGetSymbolAddress((void**)&p_dbc,  g_dbc);
    cudaGetSymbolAddress((void**)&p_hend, g_hend);
    cudaGetSymbolAddress((void**)&p_S,    g_S);
    cudaGetSymbolAddress((void**)&p_hin,  g_hin);
    cudaGetSymbolAddress((void**)&p_ygb,  g_ygb);
    cudaGetSymbolAddress((void**)&p_x2,   g_x2);
    cudaGetSymbolAddress((void**)&p_winb, g_winb);
    cudaGetSymbolAddress((void**)&p_wxpb, g_wxpb);
    cudaGetSymbolAddress((void**)&p_woutb,g_woutb);

    // 0) weights fp32 -> bf16 + positional table
    prep_kernel<<<1536, 256>>>(W_in, p_winb, W_xproj, p_wxpb, W_out, p_woutb, p_pos);

    // 1) per-(b,c) stats
    meanstd_kernel<<<B_*ENC, 32>>>(x_enc, p_mean, p_std);

    // 2) normalize + 3-tap token embed + pos -> g_xb (bf16)
    embed_kernel<<<dim3(L_/8, B_), 256>>>(x_enc, W_emb, p_mean, p_std, p_pos, p_xb);

    // 3a) xm = x @ W_in[:, :DIN]  (8192x512 @ 512x1024)
    bf16gemm_k<128,128,64,32,0><<<dim3(DIN/128, NTOK/128), 256>>>(
        p_xb, p_winb, p_xm, DM, DM, 2*DIN, DIN);

    // 3b) zg = x[last 96/seq] @ W_in[:, DIN:]  (1536x512 @ 512x1024), row-remapped A
    bf16gemm_k<64,128,32,32,1><<<dim3(DIN/128, MOUT/64), 256>>>(
        p_xb, p_winb + DIN, p_zg, DM, DM, 2*DIN, DIN);

    // 4) depthwise causal conv + silu -> g_u (fp32) + g_ub (bf16)
    conv_kernel<<<dim3(L_/16, B_), 256>>>(p_xm, conv_w, conv_b, p_u, p_ub);

    // 5) dbc = u @ W_xproj  (8192x1024 @ 1024x64)
    bf16gemm_k<64,64,16,32,0><<<dim3(1, NTOK/64), 256>>>(
        p_ub, p_wxpb, p_dbc, DIN, DIN, 64, 64);

    // 6) chunked selective scan with fused dt projection
    scanA_kernel<<<dim3(B_, DIN/128, 7), 128>>>(p_dbc, p_u, A_log, W_dt, b_dt, p_hend, p_S);
    scanB_kernel<<<dim3(B_, DIN/128), 128>>>(A_log, p_hend, p_S, p_hin);
    scanC_kernel<<<dim3(B_, DIN/128, 2), 128>>>(p_dbc, p_u, p_zg, A_log, W_dt, b_dt, Dp, p_hin, p_ygb);

    // 7) x2 = yg @ W_out  (1536x1024 @ 1024x512)
    bf16gemm_k<64,64,16,32,0><<<dim3(DM/64, MOUT/64), 256>>>(
        p_ygb, p_woutb, p_x2, DIN, DIN, DM, DM);

    // 8) out = (x2 @ W_head) * std + mean
    head_kernel<<<MOUT/8, 256>>>(p_x2, W_head, p_mean, p_std, out);
}

// round 9
// speedup vs baseline: 4.6136x; 1.2288x over previous
#include <cuda_runtime.h>
#include <cuda_bf16.h>
#include <math.h>
#include <stdint.h>

// ---------------- problem dims ----------------
#define B_   16
#define L_   512
#define ENC  7
#define DM   512
#define DIN  1024
#define DSTATE 16
#define DCONV 4
#define DTRANK 32
#define COUT 7
#define PRED 96
#define NTOK (B_*L_)          // 8192
#define MOUT (B_*PRED)        // 1536
#define NCH  8
#define CHK  64

// ---------------- scratch ----------------
__device__ float g_mean[B_*ENC];
__device__ float g_std[B_*ENC];
__device__ float g_pos[L_*DM];
__device__ __nv_bfloat16 g_xb [NTOK*DM];
__device__ float g_xm [NTOK*DIN];
__device__ float g_zg [MOUT*DIN];
__device__ __nv_bfloat16 g_ub [NTOK*DIN];     // silu(conv(xm)) bf16 only
__device__ float g_dbc[NTOK*(DTRANK+2*DSTATE)];
__device__ float g_hend[B_*NCH*DSTATE*DIN];
__device__ float g_S   [B_*NCH*DIN];
__device__ __nv_bfloat16 g_ygb[MOUT*DIN];
__device__ float g_x2 [MOUT*DM];
__device__ __nv_bfloat16 g_winb [DM*2*DIN];
__device__ __nv_bfloat16 g_wxpb [DIN*(DTRANK+2*DSTATE)];
__device__ __nv_bfloat16 g_woutb[DIN*DM];

// ---------------- helpers ----------------
__device__ __forceinline__ float softplusf(float x){
    return x > 20.f ? x : log1pf(expf(x));
}
__device__ __forceinline__ void mma_bf16(float* c, const uint32_t* a, const uint32_t* b){
    asm volatile(
      "mma.sync.aligned.m16n8k16.row.col.f32.bf16.bf16.f32 "
      "{%0,%1,%2,%3}, {%4,%5,%6,%7}, {%8,%9}, {%0,%1,%2,%3};\n"
      : "+f"(c[0]), "+f"(c[1]), "+f"(c[2]), "+f"(c[3])
      : "r"(a[0]), "r"(a[1]), "r"(a[2]), "r"(a[3]), "r"(b[0]), "r"(b[1]));
}
__device__ __forceinline__ void ldsm4(uint32_t* r, uint32_t addr){
    asm volatile("ldmatrix.sync.aligned.m8n8.x4.shared.b16 {%0,%1,%2,%3}, [%4];"
        : "=r"(r[0]), "=r"(r[1]), "=r"(r[2]), "=r"(r[3]) : "r"(addr));
}
__device__ __forceinline__ void ldsm4t(uint32_t* r, uint32_t addr){
    asm volatile("ldmatrix.sync.aligned.m8n8.x4.trans.shared.b16 {%0,%1,%2,%3}, [%4];"
        : "=r"(r[0]), "=r"(r[1]), "=r"(r[2]), "=r"(r[3]) : "r"(addr));
}
__device__ __forceinline__ void cp16(uint32_t dst, const void* src){
    asm volatile("cp.async.cg.shared.global [%0], [%1], 16;" :: "r"(dst), "l"(src));
}

// ---------------- prep: cvt (0..1023) + pos (1024..1535) + meanstd (1536..1647) --
__global__ void prep_kernel(const float* __restrict__ a, __nv_bfloat16* __restrict__ ab,
                            const float* __restrict__ b, __nv_bfloat16* __restrict__ bb,
                            const float* __restrict__ c, __nv_bfloat16* __restrict__ cb,
                            float* __restrict__ pos,
                            const float* __restrict__ x_enc,
                            float* __restrict__ mean, float* __restrict__ stdv){
    int bid = blockIdx.x;
    if (bid < 1024){
        int i = (bid*256 + threadIdx.x)*4;
        if (i < DM*2*DIN){
            float4 v = *(const float4*)(a+i);
            *(__nv_bfloat162*)(ab+i)   = __floats2bfloat162_rn(v.x, v.y);
            *(__nv_bfloat162*)(ab+i+2) = __floats2bfloat162_rn(v.z, v.w);
        }
        if (i < DIN*64){
            float4 v = *(const float4*)(b+i);
            *(__nv_bfloat162*)(bb+i)   = __floats2bfloat162_rn(v.x, v.y);
            *(__nv_bfloat162*)(bb+i+2) = __floats2bfloat162_rn(v.z, v.w);
        }
        if (i < DIN*DM){
            float4 v = *(const float4*)(c+i);
            *(__nv_bfloat162*)(cb+i)   = __floats2bfloat162_rn(v.x, v.y);
            *(__nv_bfloat162*)(cb+i+2) = __floats2bfloat162_rn(v.z, v.w);
        }
    } else if (bid < 1536){
        int l = bid - 1024;
        const float NEG_LN1E4_OVER_D = -9.210340371976184f / (float)DM;
        for (int d = threadIdx.x; d < DM; d += 256){
            float freq = expf((float)(2*(d>>1)) * NEG_LN1E4_OVER_D);
            float ang  = (float)l * freq;
            pos[l*DM + d] = (d & 1) ? cosf(ang) : sinf(ang);
        }
    } else {
        int idx = bid - 1536;                 // 0..111
        int bb_ = idx / ENC, cc = idx % ENC;
        float s = 0.f, s2 = 0.f;
        for (int l = threadIdx.x; l < L_; l += 256){
            float v = x_enc[(bb_*L_ + l)*ENC + cc];
            s += v; s2 += v*v;
        }
        __shared__ float rs[256], rs2[256];
        rs[threadIdx.x] = s; rs2[threadIdx.x] = s2;
        __syncthreads();
        for (int o = 128; o > 0; o >>= 1){
            if (threadIdx.x < o){
                rs[threadIdx.x]  += rs[threadIdx.x + o];
                rs2[threadIdx.x] += rs2[threadIdx.x + o];
            }
            __syncthreads();
        }
        if (threadIdx.x == 0){
            float m = rs[0] * (1.f/L_);
            float var = rs2[0] * (1.f/L_) - m*m;
            mean[idx] = m;
            stdv[idx] = sqrtf(var + 1e-5f);
        }
    }
}

// ---------------- embed: 8 l's per block, W_emb taps in registers ----------------
__global__ __launch_bounds__(256) void embed_kernel(
        const float* __restrict__ x_enc,
        const float* __restrict__ W_emb,
        const float* __restrict__ mean,
        const float* __restrict__ stdv,
        const float* __restrict__ pos,
        __nv_bfloat16* __restrict__ xout){
    const int l0 = blockIdx.x*8, b = blockIdx.y;
    const int tid = threadIdx.x;
    const int d0 = tid*2;
    __shared__ float s[10][ENC];
    if (tid < 10*ENC){
        int r = tid / ENC, c = tid % ENC;
        int lm = (l0 - 1 + r + L_) & (L_-1);
        s[r][c] = (x_enc[(b*L_ + lm)*ENC + c] - mean[b*ENC + c]) / stdv[b*ENC + c];
    }
    float w0[3][ENC], w1[3][ENC];
    #pragma unroll
    for (int k = 0; k < 3; k++)
        #pragma unroll
        for (int c = 0; c < ENC; c++){
            float2 wv = *reinterpret_cast<const float2*>(W_emb + (k*ENC + c)*DM + d0);
            w0[k][c] = wv.x; w1[k][c] = wv.y;
        }
    __syncthreads();
    #pragma unroll
    for (int i = 0; i < 8; i++){
        int l = l0 + i;
        float2 pv = *reinterpret_cast<const float2*>(pos + l*DM + d0);
        float a0 = pv.x, a1 = pv.y;
        #pragma unroll
        for (int k = 0; k < 3; k++)
            #pragma unroll
            for (int c = 0; c < ENC; c++){
                float sv = s[i+k][c];
                a0 = fmaf(sv, w0[k][c], a0);
                a1 = fmaf(sv, w1[k][c], a1);
            }
        *(__nv_bfloat162*)(xout + ((long)(b*L_) + l)*DM + d0) = __floats2bfloat162_rn(a0, a1);
    }
}

// ---------------- merged big GEMM: xm job (y<64) + zg job (y>=64) ----------------
// Both: K=512, BM=128, BN=128, WM=64, WN=32, lda=DM, ldb=2*DIN, ldc=DIN.
__global__ __launch_bounds__(256) void gemm_big_k(
    const __nv_bfloat16* __restrict__ Axb, const __nv_bfloat16* __restrict__ Wb,
    float* __restrict__ Cxm, float* __restrict__ Czg)
{
    constexpr int BM = 128, BN = 128, BK = 32, STG = 3;
    constexpr int WM = 64, WN = 32;
    constexpr int WARPS_N = BN/WN;
    constexpr int MT = WM/16, NT = WN/8, NT2 = WN/16;
    constexpr int BCH = BN/8;
    constexpr int K = DM, lda = DM, ldb = 2*DIN, ldc = DIN;
    __shared__ __nv_bfloat16 As[STG][BM*BK];
    __shared__ __nv_bfloat16 Bs[STG][BK*BN];

    const int tid = threadIdx.x, lane = tid & 31, wid = tid >> 5;
    const int wm = wid / WARPS_N, wn = wid % WARPS_N;
    const int quad = lane >> 3, r8 = lane & 7;
    const uint32_t aBase = (uint32_t)__cvta_generic_to_shared(&As[0][0]);
    const uint32_t bBase = (uint32_t)__cvta_generic_to_shared(&Bs[0][0]);

    const bool zjob = (blockIdx.y >= NTOK/BM);
    const int  mb   = zjob ? (blockIdx.y - NTOK/BM) : blockIdx.y;
    const __nv_bfloat16* Bg = Wb + (zjob ? DIN : 0) + blockIdx.x * BN;
    float* C = zjob ? Czg : Cxm;

    float acc[MT][NT][4] = {};

    auto load_stage = [&](int st, int k0){
        #pragma unroll
        for (int i = tid; i < BM*4; i += 256){
            int m = i >> 2, c = i & 3;
            uint32_t d = aBase + (uint32_t)(st*(BM*BK*2) + (m*BK + ((c ^ ((m>>1)&3))<<3))*2);
            long grow;
            int gm = mb*BM + m;
            if (zjob) grow = (long)(gm/PRED)*L_ + (L_-PRED) + (gm%PRED);
            else      grow = gm;
            cp16(d, Axb + grow*lda + k0 + c*8);
        }
        #pragma unroll
        for (int i = tid; i < BK*BCH; i += 256){
            int k = i / BCH, c = i % BCH;
            uint32_t d = bBase + (uint32_t)(st*(BK*BN*2) + (k*BN + ((c ^ (k&7))<<3))*2);
            cp16(d, Bg + (long)(k0+k)*ldb + c*8);
        }
    };

    const int KT = K / BK;
    load_stage(0, 0);
    asm volatile("cp.async.commit_group;");
    load_stage(1, BK);
    asm volatile("cp.async.commit_group;");

    for (int kt = 0; kt < KT; kt++){
        if (kt + 1 < KT) asm volatile("cp.async.wait_group 1;");
        else             asm volatile("cp.async.wait_group 0;");
        __syncthreads();
        if (kt + 2 < KT){
            load_stage((kt+2)%STG, (kt+2)*BK);
            asm volatile("cp.async.commit_group;");
        }
        const int st = kt % STG;
        const uint32_t aSt = aBase + st*(BM*BK*2);
        const uint32_t bSt = bBase + st*(BK*BN*2);
        #pragma unroll
        for (int ks = 0; ks < 2; ks++){
            uint32_t af[MT][4], bfr[NT2][4];
            #pragma unroll
            for (int mi = 0; mi < MT; mi++){
                int row = wm*WM + mi*16 + r8 + ((quad&1)<<3);
                int kc  = ks*2 + (quad>>1);
                uint32_t ad = aSt + (uint32_t)((row*BK + (((kc ^ ((row>>1)&3)))<<3))*2);
                ldsm4(af[mi], ad);
            }
            #pragma unroll
            for (int nj = 0; nj < NT2; nj++){
                int rk  = ks*16 + r8 + ((quad&1)<<3);
                int col = wn*WN + nj*16 + ((quad>>1)<<3);
                uint32_t bd = bSt + (uint32_t)((rk*BN + (((col>>3) ^ (rk&7))<<3))*2);
                ldsm4t(bfr[nj], bd);
            }
            #pragma unroll
            for (int mi = 0; mi < MT; mi++)
                #pragma unroll
                for (int nj = 0; nj < NT2; nj++){
                    mma_bf16(acc[mi][2*nj],   af[mi], bfr[nj]);
                    mma_bf16(acc[mi][2*nj+1], af[mi], bfr[nj]+2);
                }
        }
    }

    const int tg = lane >> 2, tq = lane & 3;
    #pragma unroll
    for (int mi = 0; mi < MT; mi++){
        long r0 = (long)mb*BM + wm*WM + mi*16 + tg;
        #pragma unroll
        for (int ni = 0; ni < NT; ni++){
            int c = blockIdx.x*BN + wn*WN + ni*8 + 2*tq;
            *reinterpret_cast<float2*>(&C[ r0   *ldc + c]) = make_float2(acc[mi][ni][0], acc[mi][ni][1]);
            *reinterpret_cast<float2*>(&C[(r0+8)*ldc + c]) = make_float2(acc[mi][ni][2], acc[mi][ni][3]);
        }
    }
}

// ---------------- generic bf16 GEMM (xproj, wout) ----------------
template<int BM, int BN, int WM, int WN>
__global__ __launch_bounds__(256) void bf16gemm_k(
    const __nv_bfloat16* __restrict__ A, const __nv_bfloat16* __restrict__ B,
    float* __restrict__ C, int K, int lda, int ldb, int ldc)
{
    constexpr int BK = 32, STG = 3;
    constexpr int WARPS_N = BN/WN;
    constexpr int MT = WM/16, NT = WN/8, NT2 = WN/16;
    constexpr int BCH = BN/8;
    __shared__ __nv_bfloat16 As[STG][BM*BK];
    __shared__ __nv_bfloat16 Bs[STG][BK*BN];

    const int tid = threadIdx.x, lane = tid & 31, wid = tid >> 5;
    const int wm = wid / WARPS_N, wn = wid % WARPS_N;
    const int quad = lane >> 3, r8 = lane & 7;
    const uint32_t aBase = (uint32_t)__cvta_generic_to_shared(&As[0][0]);
    const uint32_t bBase = (uint32_t)__cvta_generic_to_shared(&Bs[0][0]);

    const __nv_bfloat16* Ag = A + (long)blockIdx.y * BM * lda;
    const __nv_bfloat16* Bg = B + blockIdx.x * BN;

    float acc[MT][NT][4] = {};

    auto load_stage = [&](int st, int k0){
        #pragma unroll
        for (int i = tid; i < BM*4; i += 256){
            int m = i >> 2, c = i & 3;
            uint32_t d = aBase + (uint32_t)(st*(BM*BK*2) + (m*BK + ((c ^ ((m>>1)&3))<<3))*2);
            cp16(d, Ag + (long)m*lda + k0 + c*8);
        }
        #pragma unroll
        for (int i = tid; i < BK*BCH; i += 256){
            int k = i / BCH, c = i % BCH;
            uint32_t d = bBase + (uint32_t)(st*(BK*BN*2) + (k*BN + ((c ^ (k&7))<<3))*2);
            cp16(d, Bg + (long)(k0+k)*ldb + c*8);
        }
    };

    const int KT = K / BK;
    load_stage(0, 0);
    asm volatile("cp.async.commit_group;");
    load_stage(1, BK);
    asm volatile("cp.async.commit_group;");

    for (int kt = 0; kt < KT; kt++){
        if (kt + 1 < KT) asm volatile("cp.async.wait_group 1;");
        else             asm volatile("cp.async.wait_group 0;");
        __syncthreads();
        if (kt + 2 < KT){
            load_stage((kt+2)%STG, (kt+2)*BK);
            asm volatile("cp.async.commit_group;");
        }
        const int st = kt % STG;
        const uint32_t aSt = aBase + st*(BM*BK*2);
        const uint32_t bSt = bBase + st*(BK*BN*2);
        #pragma unroll
        for (int ks = 0; ks < 2; ks++){
            uint32_t af[MT][4], bfr[NT2][4];
            #pragma unroll
            for (int mi = 0; mi < MT; mi++){
                int row = wm*WM + mi*16 + r8 + ((quad&1)<<3);
                int kc  = ks*2 + (quad>>1);
                uint32_t ad = aSt + (uint32_t)((row*BK + (((kc ^ ((row>>1)&3)))<<3))*2);
                ldsm4(af[mi], ad);
            }
            #pragma unroll
            for (int nj = 0; nj < NT2; nj++){
                int rk  = ks*16 + r8 + ((quad&1)<<3);
                int col = wn*WN + nj*16 + ((quad>>1)<<3);
                uint32_t bd = bSt + (uint32_t)((rk*BN + (((col>>3) ^ (rk&7))<<3))*2);
                ldsm4t(bfr[nj], bd);
            }
            #pragma unroll
            for (int mi = 0; mi < MT; mi++)
                #pragma unroll
                for (int nj = 0; nj < NT2; nj++){
                    mma_bf16(acc[mi][2*nj],   af[mi], bfr[nj]);
                    mma_bf16(acc[mi][2*nj+1], af[mi], bfr[nj]+2);
                }
        }
    }

    const int tg = lane >> 2, tq = lane & 3;
    #pragma unroll
    for (int mi = 0; mi < MT; mi++){
        long r0 = (long)blockIdx.y*BM + wm*WM + mi*16 + tg;
        #pragma unroll
        for (int ni = 0; ni < NT; ni++){
            int c = blockIdx.x*BN + wn*WN + ni*8 + 2*tq;
            *reinterpret_cast<float2*>(&C[ r0   *ldc + c]) = make_float2(acc[mi][ni][0], acc[mi][ni][1]);
            *reinterpret_cast<float2*>(&C[(r0+8)*ldc + c]) = make_float2(acc[mi][ni][2], acc[mi][ni][3]);
        }
    }
}

// ---------------- conv: rolling-window over xm, bf16 out only ----------------
__global__ void conv_kernel(const float* __restrict__ xm,
                            const float* __restrict__ conv_w,
                            const float* __restrict__ conv_b,
                            __nv_bfloat16* __restrict__ ub){
    const int b = blockIdx.y, l0 = blockIdx.x*16;
    const int d = threadIdx.x * 4;
    float4 w0 = *reinterpret_cast<const float4*>(conv_w + 0*DIN + d);
    float4 w1 = *reinterpret_cast<const float4*>(conv_w + 1*DIN + d);
    float4 w2 = *reinterpret_cast<const float4*>(conv_w + 2*DIN + d);
    float4 w3 = *reinterpret_cast<const float4*>(conv_w + 3*DIN + d);
    float4 bv = *reinterpret_cast<const float4*>(conv_b + d);
    float4 x0, x1, x2;
    if (l0 > 0){
        x0 = *reinterpret_cast<const float4*>(xm + ((long)(b*L_)+l0-3)*DIN + d);
        x1 = *reinterpret_cast<const float4*>(xm + ((long)(b*L_)+l0-2)*DIN + d);
        x2 = *reinterpret_cast<const float4*>(xm + ((long)(b*L_)+l0-1)*DIN + d);
    } else {
        x0 = make_float4(0,0,0,0); x1 = x0; x2 = x0;
    }
    #pragma unroll
    for (int tt = 0; tt < 16; tt++){
        long row = (long)(b*L_) + l0 + tt;
        float4 x3 = *reinterpret_cast<const float4*>(xm + row*DIN + d);
        float4 a = bv;
        a.x = fmaf(w0.x,x0.x, fmaf(w1.x,x1.x, fmaf(w2.x,x2.x, fmaf(w3.x,x3.x, a.x))));
        a.y = fmaf(w0.y,x0.y, fmaf(w1.y,x1.y, fmaf(w2.y,x2.y, fmaf(w3.y,x3.y, a.y))));
        a.z = fmaf(w0.z,x0.z, fmaf(w1.z,x1.z, fmaf(w2.z,x2.z, fmaf(w3.z,x3.z, a.z))));
        a.w = fmaf(w0.w,x0.w, fmaf(w1.w,x1.w, fmaf(w2.w,x2.w, fmaf(w3.w,x3.w, a.w))));
        float4 o;
        o.x = a.x / (1.f + __expf(-a.x));
        o.y = a.y / (1.f + __expf(-a.y));
        o.z = a.z / (1.f + __expf(-a.z));
        o.w = a.w / (1.f + __expf(-a.w));
        *(__nv_bfloat162*)(ub + row*DIN + d)     = __floats2bfloat162_rn(o.x, o.y);
        *(__nv_bfloat162*)(ub + row*DIN + d + 2) = __floats2bfloat162_rn(o.z, o.w);
        x0 = x1; x1 = x2; x2 = x3;
    }
}

// ---------------- scan A: local scans chunks 0..6, dt fused ----------------
__global__ void scanA_kernel(const float* __restrict__ dbc,
                             const __nv_bfloat16* __restrict__ ub,
                             const float* __restrict__ A_log,
                             const float* __restrict__ W_dt,
                             const float* __restrict__ b_dt,
                             float* __restrict__ hend,
                             float* __restrict__ Ssum){
    const int b = blockIdx.x, c = blockIdx.z;
    const int d = blockIdx.y * 128 + threadIdx.x;
    const int t0 = c * CHK;
    float h[DSTATE], An[DSTATE], wdt[DTRANK];
    #pragma unroll
    for (int n = 0; n < DSTATE; n++){
        h[n]  = 0.f;
        An[n] = -expf(A_log[d*DSTATE + n]);
    }
    #pragma unroll
    for (int k = 0; k < DTRANK; k++)
        wdt[k] = W_dt[k*DIN + d];
    const float bdt = b_dt[d];
    __shared__ float sRow[CHK][64];
    for (int i = threadIdx.x; i < CHK*16; i += 128){
        int tt = i >> 4, c4 = i & 15;
        *reinterpret_cast<float4*>(&sRow[tt][c4*4]) =
            *reinterpret_cast<const float4*>(dbc + ((long)(b*L_) + (t0+tt))*64 + c4*4);
    }
    __syncthreads();
    float S = 0.f;
    for (int tt = 0; tt < CHK; tt++){
        float dot = bdt;
        #pragma unroll
        for (int k = 0; k < DTRANK; k++)
            dot = fmaf(sRow[tt][k], wdt[k], dot);
        float dtv = softplusf(dot);
        float uv  = __bfloat162float(ub[((long)(b*L_) + t0 + tt)*DIN + d]);
        float dtu = dtv * uv;
        S += dtv;
        #pragma unroll
        for (int n = 0; n < DSTATE; n++)
            h[n] = fmaf(__expf(dtv * An[n]), h[n], dtu * sRow[tt][DTRANK + n]);
    }
    #pragma unroll
    for (int n = 0; n < DSTATE; n++)
        hend[((long)(b*NCH + c)*DSTATE + n)*DIN + d] = h[n];
    Ssum[(long)(b*NCH + c)*DIN + d] = S;
}

// ---------------- scan C: inline combine + rescan chunks 6,7, emit gated y ------
__global__ void scanC_kernel(const float* __restrict__ dbc,
                             const __nv_bfloat16* __restrict__ ub,
                             const float* __restrict__ zg,
                             const float* __restrict__ A_log,
                             const float* __restrict__ W_dt,
                             const float* __restrict__ b_dt,
                             const float* __restrict__ Dp,
                             const float* __restrict__ hend,
                             const float* __restrict__ Ssum,
                             __nv_bfloat16* __restrict__ yg){
    const int b = blockIdx.x, ci = blockIdx.z;
    const int d = blockIdx.y * 128 + threadIdx.x;
    const int t0 = (6 + ci) * CHK;
    float h[DSTATE], An[DSTATE], wdt[DTRANK];
    #pragma unroll
    for (int n = 0; n < DSTATE; n++){
        h[n]  = 0.f;
        An[n] = -expf(A_log[d*DSTATE + n]);
    }
    // inline combine of chunks 0..(5+ci)
    for (int c = 0; c < 6 + ci; c++){
        float S = Ssum[(long)(b*NCH + c)*DIN + d];
        #pragma unroll
        for (int n = 0; n < DSTATE; n++)
            h[n] = fmaf(__expf(An[n]*S), h[n],
                        hend[((long)(b*NCH + c)*DSTATE + n)*DIN + d]);
    }
    #pragma unroll
    for (int k = 0; k < DTRANK; k++)
        wdt[k] = W_dt[k*DIN + d];
    const float bdt = b_dt[d];
    const float Dv = Dp[d];
    __shared__ float sRow[CHK][64];
    for (int i = threadIdx.x; i < CHK*16; i += 128){
        int tt = i >> 4, c4 = i & 15;
        *reinterpret_cast<float4*>(&sRow[tt][c4*4]) =
            *reinterpret_cast<const float4*>(dbc + ((long)(b*L_) + (t0+tt))*64 + c4*4);
    }
    __syncthreads();
    for (int tt = 0; tt < CHK; tt++){
        int t = t0 + tt;
        long row = (long)(b*L_) + t;
        float dot = bdt;
        #pragma unroll
        for (int k = 0; k < DTRANK; k++)
            dot = fmaf(sRow[tt][k], wdt[k], dot);
        float dtv = softplusf(dot);
        float uv  = __bfloat162float(ub[row*DIN + d]);
        float dtu = dtv * uv;
        float y = 0.f;
        #pragma unroll
        for (int n = 0; n < DSTATE; n++){
            h[n] = fmaf(__expf(dtv * An[n]), h[n], dtu * sRow[tt][DTRANK + n]);
            y = fmaf(h[n], sRow[tt][DTRANK + DSTATE + n], y);
        }
        if (t >= L_ - PRED){
            long orow = (long)(b*PRED) + (t - (L_-PRED));
            float zv = zg[orow*DIN + d];
            float sg = 1.f / (1.f + __expf(-zv));
            yg[orow*DIN + d] = __float2bfloat16((y + uv*Dv) * (zv * sg));
        }
    }
}

// ---------------- head: warp-per-row GEMV + denorm ----------------
__global__ void head_kernel(const float* __restrict__ x2,
                            const float* __restrict__ W_head,
                            const float* __restrict__ mean,
                            const float* __restrict__ stdv,
                            float* __restrict__ out){
    __shared__ float sw[DM*COUT];
    for (int i = threadIdx.x; i < DM*COUT; i += 256)
        sw[i] = W_head[i];
    __syncthreads();
    int warp = threadIdx.x >> 5, lane = threadIdx.x & 31;
    int m = blockIdx.x*8 + warp;
    float acc[COUT] = {};
    for (int k = lane; k < DM; k += 32){
        float xv = x2[(long)m*DM + k];
        #pragma unroll
        for (int c = 0; c < COUT; c++)
            acc[c] = fmaf(xv, sw[k*COUT + c], acc[c]);
    }
    #pragma unroll
    for (int c = 0; c < COUT; c++)
        #pragma unroll
        for (int o = 16; o > 0; o >>= 1)
            acc[c] += __shfl_xor_sync(0xffffffffu, acc[c], o);
    if (lane == 0){
        int b = m / PRED;
        #pragma unroll
        for (int c = 0; c < COUT; c++)
            out[(long)m*COUT + c] = acc[c] * stdv[b*ENC + c] + mean[b*ENC + c];
    }
}

// ---------------- launcher ----------------
extern "C" void kernel_launch(void* const* d_in, const int* in_sizes, int n_in,
                              void* d_out, int out_size){
    const float* x_enc  = (const float*)d_in[0];
    const float* W_emb  = (const float*)d_in[1];
    const float* W_in   = (const float*)d_in[2];
    const float* conv_w = (const float*)d_in[3];
    const float* conv_b = (const float*)d_in[4];
    const float* W_xproj= (const float*)d_in[5];
    const float* W_dt   = (const float*)d_in[6];
    const float* b_dt   = (const float*)d_in[7];
    const float* A_log  = (const float*)d_in[8];
    const float* Dp     = (const float*)d_in[9];
    const float* W_out  = (const float*)d_in[10];
    const float* W_head = (const float*)d_in[11];
    float* out = (float*)d_out;

    float *p_mean,*p_std,*p_pos,*p_xm,*p_zg,*p_dbc,*p_x2,*p_hend,*p_S;
    __nv_bfloat16 *p_xb,*p_ub,*p_ygb,*p_winb,*p_wxpb,*p_woutb;
    cudaGetSymbolAddress((void**)&p_mean, g_mean);
    cudaGetSymbolAddress((void**)&p_std,  g_std);
    cudaGetSymbolAddress((void**)&p_pos,  g_pos);
    cudaGetSymbolAddress((void**)&p_xb,   g_xb);
    cudaGetSymbolAddress((void**)&p_xm,   g_xm);
    cudaGetSymbolAddress((void**)&p_zg,   g_zg);
    cudaGetSymbolAddress((void**)&p_ub,   g_ub);
    cudaGetSymbolAddress((void**)&p_dbc,  g_dbc);
    cudaGetSymbolAddress((void**)&p_hend, g_hend);
    cudaGetSymbolAddress((void**)&p_S,    g_S);
    cudaGetSymbolAddress((void**)&p_ygb,  g_ygb);
    cudaGetSymbolAddress((void**)&p_x2,   g_x2);
    cudaGetSymbolAddress((void**)&p_winb, g_winb);
    cudaGetSymbolAddress((void**)&p_wxpb, g_wxpb);
    cudaGetSymbolAddress((void**)&p_woutb,g_woutb);

    // 1) weights cvt + pos table + per-(b,c) stats (one launch)
    prep_kernel<<<1648, 256>>>(W_in, p_winb, W_xproj, p_wxpb, W_out, p_woutb,
                               p_pos, x_enc, p_mean, p_std);

    // 2) normalize + 3-tap token embed + pos -> g_xb (bf16)
    embed_kernel<<<dim3(L_/8, B_), 256>>>(x_enc, W_emb, p_mean, p_std, p_pos, p_xb);

    // 3) xm (8192x1024) + zg (1536x1024) in ONE launch
    gemm_big_k<<<dim3(DIN/128, NTOK/128 + MOUT/128), 256>>>(p_xb, p_winb, p_xm, p_zg);

    // 4) depthwise causal conv + silu -> g_ub (bf16 only)
    conv_kernel<<<dim3(L_/16, B_), 256>>>(p_xm, conv_w, conv_b, p_ub);

    // 5) dbc = u @ W_xproj  (8192x1024 @ 1024x64)
    bf16gemm_k<64,64,16,32><<<dim3(1, NTOK/64), 256>>>(
        p_ub, p_wxpb, p_dbc, DIN, DIN, 64, 64);

    // 6) chunked selective scan (dt fused; combine folded into scanC)
    scanA_kernel<<<dim3(B_, DIN/128, 7), 128>>>(p_dbc, p_ub, A_log, W_dt, b_dt, p_hend, p_S);
    scanC_kernel<<<dim3(B_, DIN/128, 2), 128>>>(p_dbc, p_ub, p_zg, A_log, W_dt, b_dt, Dp,
                                                p_hend, p_S, p_ygb);

    // 7) x2 = yg @ W_out  (1536x1024 @ 1024x512)
    bf16gemm_k<64,64,16,32><<<dim3(DM/64, MOUT/64), 256>>>(
        p_ygb, p_woutb, p_x2, DIN, DIN, DM, DM);

    // 8) out = (x2 @ W_head) * std + mean
    head_kernel<<<MOUT/8, 256>>>(p_x2, W_head, p_mean, p_std, out);
}